// round 2
// baseline (speedup 1.0000x reference)
#include <cuda_runtime.h>
#include <cuda_bf16.h>
#include <math.h>

// ---------------- problem constants ----------------
#define BB    16
#define SS    16
#define DD    4096
#define HH    32
#define KVH   8
#define HDIM  128
#define NREP  4
#define MAXS  4096
#define MROWS 256          // B*S
#define KVLEN 4096         // start_pos + S == MAX_S

// ---------------- device scratch (no allocs allowed) ----------------
__device__ float g_Q  [MROWS * (HH  * HDIM)];   // rope'd Q,  [m][h*128+d]
__device__ float g_Kn [MROWS * (KVH * HDIM)];   // rope'd new K, [m][kvh*128+d]
__device__ float g_Vn [MROWS * (KVH * HDIM)];   // new V
__device__ float g_ctx[MROWS * (HH  * HDIM)];   // attention output

// ---------------- generic fp32 GEMM: C[M,N] = A[M,K] @ B[K,N] ----------------
// BM=BN=64, BK=16, 256 threads, 4x4 per-thread microtile.
__global__ __launch_bounds__(256) void sgemm64(const float* __restrict__ A,
                                               const float* __restrict__ B,
                                               float* __restrict__ C,
                                               int M, int N, int K)
{
    __shared__ float As[16][64];   // transposed A tile
    __shared__ float Bs[16][64];

    const int t  = threadIdx.x;
    const int bm = blockIdx.y * 64;
    const int bn = blockIdx.x * 64;
    const int tx = t & 15;
    const int ty = t >> 4;

    const int arow = t >> 2;          // 0..63
    const int acol = (t & 3) << 2;    // 0,4,8,12
    const int brow = t >> 4;          // 0..15
    const int bcol = (t & 15) << 2;   // 0..60

    const float* Ap = A + (size_t)(bm + arow) * K + acol;
    const float* Bp = B + (size_t)brow * N + bn + bcol;

    float acc[4][4];
#pragma unroll
    for (int i = 0; i < 4; i++)
#pragma unroll
        for (int j = 0; j < 4; j++) acc[i][j] = 0.f;

    for (int k0 = 0; k0 < K; k0 += 16) {
        float4 av = *(const float4*)(Ap + k0);
        float4 bv = *(const float4*)(Bp + (size_t)k0 * N);
        As[acol + 0][arow] = av.x;
        As[acol + 1][arow] = av.y;
        As[acol + 2][arow] = av.z;
        As[acol + 3][arow] = av.w;
        *(float4*)&Bs[brow][bcol] = bv;
        __syncthreads();

#pragma unroll
        for (int kk = 0; kk < 16; kk++) {
            float4 a = *(const float4*)&As[kk][ty << 2];
            float4 b = *(const float4*)&Bs[kk][tx << 2];
            float ar[4] = {a.x, a.y, a.z, a.w};
            float br[4] = {b.x, b.y, b.z, b.w};
#pragma unroll
            for (int i = 0; i < 4; i++)
#pragma unroll
                for (int j = 0; j < 4; j++)
                    acc[i][j] = fmaf(ar[i], br[j], acc[i][j]);
        }
        __syncthreads();
    }

#pragma unroll
    for (int i = 0; i < 4; i++) {
        float4 v = make_float4(acc[i][0], acc[i][1], acc[i][2], acc[i][3]);
        *(float4*)(C + (size_t)(bm + (ty << 2) + i) * N + bn + (tx << 2)) = v;
    }
}

// ---------------- RoPE (in place on g_Q and g_Kn) ----------------
__global__ void rope_kernel(const int* __restrict__ spp)
{
    const int nq = MROWS * HH  * (HDIM / 2);
    const int nk = MROWS * KVH * (HDIM / 2);
    int idx = blockIdx.x * blockDim.x + threadIdx.x;
    if (idx >= nq + nk) return;
    const int sp = *spp;

    float* buf; int nh; int i;
    if (idx < nq) { buf = g_Q;  nh = HH;  i = idx; }
    else          { buf = g_Kn; nh = KVH; i = idx - nq; }

    const int j = i & 63;              // pair index 0..63
    const int h = (i >> 6) % nh;
    const int m = i / (64 * nh);
    const int s = m & (SS - 1);

    float p     = (float)(sp + s);
    float theta = powf(10000.0f, -(float)(2 * j) / 128.0f);
    float f     = p * theta;
    float sn, c;
    sincosf(f, &sn, &c);

    float* ptr = buf + ((size_t)m * nh + h) * HDIM + (j << 1);
    float xr = ptr[0], xi = ptr[1];
    ptr[0] = xr * c - xi * sn;
    ptr[1] = xr * sn + xi * c;
}

// ---------------- flash attention: one CTA per (b, kvh), 64 q-rows ----------------
// smem: Qt[128][64] | sKV (K as [128][64] then V as [64][128]) | Pt[64key][64row] | rowM/L/C[64]
#define ATTN_SMEM_FLOATS (128*64 + 128*64 + 64*64 + 192)
#define ATTN_SMEM_BYTES  (ATTN_SMEM_FLOATS * 4)

__global__ __launch_bounds__(256) void attn_kernel(const float* __restrict__ cacheK,
                                                   const float* __restrict__ cacheV,
                                                   const int* __restrict__ spp)
{
    extern __shared__ float sm[];
    float* Qt   = sm;                       // [kk][r]  128*64
    float* sKV  = sm + 128 * 64;            // K: [kk][c] ; V: [c][d]
    float* Pt   = sm + 2 * 128 * 64;        // [key][row] 64*64
    float* rowM = Pt + 64 * 64;
    float* rowL = rowM + 64;
    float* rowC = rowL + 64;

    const int b   = blockIdx.x >> 3;
    const int kvh = blockIdx.x & 7;
    const int sp  = *spp;
    const int t   = threadIdx.x;

    // load Q tile transposed: row r = rep*16 + s  ->  head h = kvh*4 + rep
    for (int i = t; i < 64 * 32; i += 256) {
        int r  = i >> 5;
        int d4 = (i & 31) << 2;
        int rep = r >> 4, s = r & 15;
        const float4 v = *(const float4*)(g_Q +
            ((size_t)(b * SS + s) * HH + (kvh * NREP + rep)) * HDIM + d4);
        Qt[(d4 + 0) * 64 + r] = v.x;
        Qt[(d4 + 1) * 64 + r] = v.y;
        Qt[(d4 + 2) * 64 + r] = v.z;
        Qt[(d4 + 3) * 64 + r] = v.w;
    }
    if (t < 64) { rowM[t] = __int_as_float(0xff800000); rowL[t] = 0.f; }

    const int srow = (t >> 4) << 2;   // 0..60 (query rows this thread owns)
    const int scol = (t & 15) << 2;   // 0..60 (score cols / ctx cols base)

    float acc[4][8];
#pragma unroll
    for (int i = 0; i < 4; i++)
#pragma unroll
        for (int j = 0; j < 8; j++) acc[i][j] = 0.f;

    const float scale = 0.08838834764831845f;   // 1/sqrt(128)

    for (int t0 = 0; t0 < KVLEN; t0 += 64) {
        __syncthreads();   // prior iteration done with sKV/Pt

        // ---- load K chunk transposed into sKV[kk][c] ----
        for (int i = t; i < 64 * 32; i += 256) {
            int r  = i >> 5;
            int d4 = (i & 31) << 2;
            int tk = t0 + r;
            float4 v;
            if (tk < sp)
                v = *(const float4*)(cacheK +
                    (((size_t)b * MAXS + tk) * KVH + kvh) * HDIM + d4);
            else
                v = *(const float4*)(g_Kn +
                    ((size_t)(b * SS + (tk - sp)) * KVH + kvh) * HDIM + d4);
            sKV[(d4 + 0) * 64 + r] = v.x;
            sKV[(d4 + 1) * 64 + r] = v.y;
            sKV[(d4 + 2) * 64 + r] = v.z;
            sKV[(d4 + 3) * 64 + r] = v.w;
        }
        __syncthreads();

        // ---- scores: S[r][c] = sum_k Qt[k][r] * K[k][c] ----
        float sacc[4][4];
#pragma unroll
        for (int i = 0; i < 4; i++)
#pragma unroll
            for (int j = 0; j < 4; j++) sacc[i][j] = 0.f;

#pragma unroll 8
        for (int kk = 0; kk < HDIM; kk++) {
            float4 a = *(const float4*)&Qt [kk * 64 + srow];
            float4 k = *(const float4*)&sKV[kk * 64 + scol];
            float ar[4] = {a.x, a.y, a.z, a.w};
            float kr[4] = {k.x, k.y, k.z, k.w};
#pragma unroll
            for (int i = 0; i < 4; i++)
#pragma unroll
                for (int j = 0; j < 4; j++)
                    sacc[i][j] = fmaf(ar[i], kr[j], sacc[i][j]);
        }
#pragma unroll
        for (int i = 0; i < 4; i++)
#pragma unroll
            for (int j = 0; j < 4; j++)
                Pt[(scol + j) * 64 + (srow + i)] = sacc[i][j] * scale;
        __syncthreads();

        // ---- load V chunk (natural layout) into sKV[c][d] ----
        for (int i = t; i < 64 * 32; i += 256) {
            int r  = i >> 5;
            int d4 = (i & 31) << 2;
            int tk = t0 + r;
            float4 v;
            if (tk < sp)
                v = *(const float4*)(cacheV +
                    (((size_t)b * MAXS + tk) * KVH + kvh) * HDIM + d4);
            else
                v = *(const float4*)(g_Vn +
                    ((size_t)(b * SS + (tk - sp)) * KVH + kvh) * HDIM + d4);
            *(float4*)&sKV[r * HDIM + d4] = v;
        }

        // ---- online softmax over this chunk (one thread per query row) ----
        if (t < 64) {
            const int r = t;
            float mo = rowM[r];
            float mx = mo;
            for (int c = 0; c < 64; c++) mx = fmaxf(mx, Pt[c * 64 + r]);
            float corr = expf(mo - mx);          // 0 on first chunk (mo = -inf)
            float suml = 0.f;
            for (int c = 0; c < 64; c++) {
                float e = expf(Pt[c * 64 + r] - mx);
                Pt[c * 64 + r] = e;
                suml += e;
            }
            rowM[r] = mx;
            rowL[r] = rowL[r] * corr + suml;
            rowC[r] = corr;
        }
        __syncthreads();

        // ---- rescale accumulators, then ctx += P @ V ----
        float cr[4];
#pragma unroll
        for (int i = 0; i < 4; i++) cr[i] = rowC[srow + i];
#pragma unroll
        for (int i = 0; i < 4; i++)
#pragma unroll
            for (int j = 0; j < 8; j++) acc[i][j] *= cr[i];

#pragma unroll 4
        for (int j = 0; j < 64; j++) {
            float4 p  = *(const float4*)&Pt [j * 64 + srow];
            float4 v0 = *(const float4*)&sKV[j * HDIM + scol];
            float4 v1 = *(const float4*)&sKV[j * HDIM + scol + 64];
            float pr[4] = {p.x, p.y, p.z, p.w};
            float va[4] = {v0.x, v0.y, v0.z, v0.w};
            float vb[4] = {v1.x, v1.y, v1.z, v1.w};
#pragma unroll
            for (int i = 0; i < 4; i++) {
#pragma unroll
                for (int d = 0; d < 4; d++) {
                    acc[i][d]     = fmaf(pr[i], va[d], acc[i][d]);
                    acc[i][d + 4] = fmaf(pr[i], vb[d], acc[i][d + 4]);
                }
            }
        }
    }

    // ---- normalize + store ctx ----
    float inv[4];
#pragma unroll
    for (int i = 0; i < 4; i++) inv[i] = 1.f / rowL[srow + i];
#pragma unroll
    for (int i = 0; i < 4; i++) {
        int r = srow + i;
        int rep = r >> 4, s = r & 15;
        float* dst = g_ctx + ((size_t)(b * SS + s) * HH + (kvh * NREP + rep)) * HDIM;
        float4 o0 = make_float4(acc[i][0] * inv[i], acc[i][1] * inv[i],
                                acc[i][2] * inv[i], acc[i][3] * inv[i]);
        float4 o1 = make_float4(acc[i][4] * inv[i], acc[i][5] * inv[i],
                                acc[i][6] * inv[i], acc[i][7] * inv[i]);
        *(float4*)(dst + scol)      = o0;
        *(float4*)(dst + scol + 64) = o1;
    }
}

// ---------------- launch ----------------
extern "C" void kernel_launch(void* const* d_in, const int* in_sizes, int n_in,
                              void* d_out, int out_size)
{
    const float* x      = (const float*)d_in[0];
    const float* Wq     = (const float*)d_in[1];
    const float* Wk     = (const float*)d_in[2];
    const float* Wv     = (const float*)d_in[3];
    const float* Wo     = (const float*)d_in[4];
    const float* cacheK = (const float*)d_in[5];
    const float* cacheV = (const float*)d_in[6];
    const int*   spp    = (const int*)  d_in[7];
    float*       out    = (float*)d_out;
    (void)in_sizes; (void)n_in; (void)out_size;

    void *qp, *kp, *vp, *cp;
    cudaGetSymbolAddress(&qp, g_Q);
    cudaGetSymbolAddress(&kp, g_Kn);
    cudaGetSymbolAddress(&vp, g_Vn);
    cudaGetSymbolAddress(&cp, g_ctx);

    cudaFuncSetAttribute(attn_kernel,
                         cudaFuncAttributeMaxDynamicSharedMemorySize,
                         ATTN_SMEM_BYTES);

    dim3 blk(256);
    // QKV projections
    sgemm64<<<dim3(64, 4), blk>>>(x, Wq, (float*)qp, MROWS, 4096, 4096);
    sgemm64<<<dim3(16, 4), blk>>>(x, Wk, (float*)kp, MROWS, 1024, 4096);
    sgemm64<<<dim3(16, 4), blk>>>(x, Wv, (float*)vp, MROWS, 1024, 4096);
    // RoPE on Q and new K (in place)
    {
        int total = MROWS * HH * 64 + MROWS * KVH * 64;
        rope_kernel<<<(total + 255) / 256, 256>>>(spp);
    }
    // attention over full cache (new rows read from scratch, cache untouched)
    attn_kernel<<<BB * KVH, blk, ATTN_SMEM_BYTES>>>(cacheK, cacheV, spp);
    // output projection -> d_out
    sgemm64<<<dim3(64, 4), blk>>>((const float*)cp, Wo, out, MROWS, 4096, 4096);
}

// round 5
// speedup vs baseline: 2.6749x; 2.6749x over previous
#include <cuda_runtime.h>
#include <cuda_bf16.h>
#include <math.h>
#include <stdint.h>

// ---------------- problem constants ----------------
#define BB    16
#define SS    16
#define HH    32
#define KVH   8
#define HDIM  128
#define MAXS  4096
#define MROWS 256
#define DK    4096
#define KVLEN 4096

typedef __nv_bfloat16  bf16;
typedef __nv_bfloat162 bf162;

// ---------------- device scratch ----------------
__device__ bf16 g_Xhi[MROWS * DK], g_Xlo[MROWS * DK];
__device__ bf16 g_Chi[MROWS * DK], g_Clo[MROWS * DK];
__device__ bf16 g_WqTh[4096 * 4096], g_WqTl[4096 * 4096];
__device__ bf16 g_WkTh[1024 * 4096], g_WkTl[1024 * 4096];
__device__ bf16 g_WvTh[1024 * 4096], g_WvTl[1024 * 4096];
__device__ bf16 g_WoTh[4096 * 4096], g_WoTl[4096 * 4096];
__device__ float g_Q [MROWS * 4096];
__device__ float g_Kn[MROWS * 1024];
__device__ float g_Vn[MROWS * 1024];

// ---------------- PTX helpers (baseline ISA only — no tcgen05 on compute_103) ----------------
__device__ __forceinline__ uint32_t smem_u32(const void* p) {
    uint32_t a;
    asm("{ .reg .u64 t; cvta.to.shared.u64 t, %1; cvt.u32.u64 %0, t; }" : "=r"(a) : "l"(p));
    return a;
}
#define LDSM4(r, addr) \
    asm volatile("ldmatrix.sync.aligned.m8n8.x4.shared.b16 {%0,%1,%2,%3}, [%4];" \
        : "=r"((r)[0]), "=r"((r)[1]), "=r"((r)[2]), "=r"((r)[3]) : "r"(addr))
#define LDSM4T(r, addr) \
    asm volatile("ldmatrix.sync.aligned.m8n8.x4.trans.shared.b16 {%0,%1,%2,%3}, [%4];" \
        : "=r"((r)[0]), "=r"((r)[1]), "=r"((r)[2]), "=r"((r)[3]) : "r"(addr))
#define MMA16816(d, a, b0, b1) \
    asm volatile("mma.sync.aligned.m16n8k16.row.col.f32.bf16.bf16.f32 " \
        "{%0,%1,%2,%3}, {%4,%5,%6,%7}, {%8,%9}, {%0,%1,%2,%3};" \
        : "+f"((d)[0]), "+f"((d)[1]), "+f"((d)[2]), "+f"((d)[3]) \
        : "r"((a)[0]), "r"((a)[1]), "r"((a)[2]), "r"((a)[3]), "r"(b0), "r"(b1))
#define CP16(dst, src) \
    asm volatile("cp.async.cg.shared.global [%0], [%1], 16;" :: "r"(dst), "l"(src))
#define CP_COMMIT() asm volatile("cp.async.commit_group;" ::: "memory")
#define CP_WAIT0()  asm volatile("cp.async.wait_group 0;" ::: "memory")
#define CP_WAIT1()  asm volatile("cp.async.wait_group 1;" ::: "memory")

__device__ __forceinline__ void cvt_hilo4(float4 v, bf162& h01, bf162& h23,
                                          bf162& l01, bf162& l23) {
    h01.x = __float2bfloat16(v.x); h01.y = __float2bfloat16(v.y);
    h23.x = __float2bfloat16(v.z); h23.y = __float2bfloat16(v.w);
    l01.x = __float2bfloat16(v.x - __bfloat162float(h01.x));
    l01.y = __float2bfloat16(v.y - __bfloat162float(h01.y));
    l23.x = __float2bfloat16(v.z - __bfloat162float(h23.x));
    l23.y = __float2bfloat16(v.w - __bfloat162float(h23.y));
}

// ---------------- conversion kernels ----------------
__global__ void conv_hilo(const float* __restrict__ in, bf16* __restrict__ hi,
                          bf16* __restrict__ lo, int n)
{
    int i = blockIdx.x * blockDim.x + threadIdx.x;
    if (i >= n) return;
    float v = in[i];
    bf16 h = __float2bfloat16(v);
    hi[i] = h;
    lo[i] = __float2bfloat16(v - __bfloat162float(h));
}

// transpose + convert: W[Kg rows][N cols] fp32 -> T[N][Kg] bf16 hi/lo
__global__ __launch_bounds__(256) void convT(const float* __restrict__ W,
                                             bf16* __restrict__ Th, bf16* __restrict__ Tl,
                                             int Kg, int N)
{
    __shared__ float tile[64][65];
    const int t  = threadIdx.x;
    const int bn = blockIdx.x * 64;
    const int bk = blockIdx.y * 64;
    for (int i = t; i < 4096; i += 256) {
        int r = i >> 6, c = i & 63;
        tile[r][c] = W[(size_t)(bk + r) * N + bn + c];
    }
    __syncthreads();
    for (int i = t; i < 4096; i += 256) {
        int n = i >> 6, k = i & 63;
        float v = tile[k][n];
        bf16 h = __float2bfloat16(v);
        size_t o = (size_t)(bn + n) * Kg + bk + k;
        Th[o] = h;
        Tl[o] = __float2bfloat16(v - __bfloat162float(h));
    }
}

// ---------------- RoPE (in place on g_Q and g_Kn) ----------------
__global__ void rope_kernel(const int* __restrict__ spp)
{
    const int nq = MROWS * HH  * (HDIM / 2);
    const int nk = MROWS * KVH * (HDIM / 2);
    int idx = blockIdx.x * blockDim.x + threadIdx.x;
    if (idx >= nq + nk) return;
    const int sp = *spp;

    float* buf; int nh; int i;
    if (idx < nq) { buf = g_Q;  nh = HH;  i = idx; }
    else          { buf = g_Kn; nh = KVH; i = idx - nq; }

    const int j = i & 63;
    const int h = (i >> 6) % nh;
    const int m = i / (64 * nh);
    const int s = m & (SS - 1);

    float p     = (float)(sp + s);
    float theta = powf(10000.0f, -(float)(2 * j) / 128.0f);
    float f     = p * theta;
    float sn, c;
    sincosf(f, &sn, &c);

    float* ptr = buf + ((size_t)m * nh + h) * HDIM + (j << 1);
    float xr = ptr[0], xi = ptr[1];
    ptr[0] = xr * c - xi * sn;
    ptr[1] = xr * sn + xi * c;
}

// ================= HMMA hi/lo GEMM: C = A[256,4096] @ B^T, tile 128x64 =================
// 3-way fused output segments (Q/K/V share A). 3-stage cp.async pipeline, chunk K=32.
// SMEM stage layout: Ahi[128][80B] Alo Bhi[64][80B] Blo  (80B = 64B data + 16 pad)
#define G_STAGE 30720
#define G_SMEM  (3 * G_STAGE)

__global__ __launch_bounds__(256) void hgemm(
    const bf16* __restrict__ Ah, const bf16* __restrict__ Al,
    const bf16* __restrict__ B0h, const bf16* __restrict__ B0l, float* __restrict__ C0, int N0,
    const bf16* __restrict__ B1h, const bf16* __restrict__ B1l, float* __restrict__ C1, int N1,
    const bf16* __restrict__ B2h, const bf16* __restrict__ B2l, float* __restrict__ C2, int N2)
{
    extern __shared__ char smg[];
    const int t = threadIdx.x, w = t >> 5, lane = t & 31;
    const int wm = w >> 2, wn = w & 3;          // 2 m-warps x 4 n-warps
    const int bm = blockIdx.y * 128;

    // segment select
    int xt = blockIdx.x;
    const int t0n = N0 >> 6, t1n = N1 >> 6;
    const bf16 *Bh, *Bl; float* C; int Nseg, bn;
    if (xt < t0n)            { Bh = B0h; Bl = B0l; C = C0; Nseg = N0; bn = xt * 64; }
    else if (xt < t0n + t1n) { Bh = B1h; Bl = B1l; C = C1; Nseg = N1; bn = (xt - t0n) * 64; }
    else                     { Bh = B2h; Bl = B2l; C = C2; Nseg = N2; bn = (xt - t0n - t1n) * 64; }

    const uint32_t sbase = smem_u32(smg);

    // stage copier: 1536 x 16B cp.async
    auto copy_stage = [&](int slot, int ch) {
        const int k0 = ch * 32;
        char* base = smg + slot * G_STAGE;
#pragma unroll
        for (int j = 0; j < 6; j++) {
            int idx = j * 256 + t;
            const bf16* src; uint32_t dst;
            if (idx < 1024) {
                int hl = idx >> 9, i = idx & 511, r = i >> 2, c = i & 3;
                src = (hl ? Al : Ah) + (size_t)(bm + r) * DK + k0 + c * 8;
                dst = smem_u32(base + hl * 10240 + r * 80 + c * 16);
            } else {
                int q = idx - 1024, hl = q >> 8, i = q & 255, r = i >> 2, c = i & 3;
                src = (hl ? Bl : Bh) + (size_t)(bn + r) * DK + k0 + c * 8;
                dst = smem_u32(base + 20480 + hl * 5120 + r * 80 + c * 16);
            }
            CP16(dst, src);
        }
    };

    float acc[4][2][4];
#pragma unroll
    for (int a = 0; a < 4; a++)
#pragma unroll
        for (int bq = 0; bq < 2; bq++)
#pragma unroll
            for (int cix = 0; cix < 4; cix++) acc[a][bq][cix] = 0.f;

    const int NCH = DK / 32;       // 128
    copy_stage(0, 0); CP_COMMIT();
    copy_stage(1, 1); CP_COMMIT();

    const uint32_t a_lane = (lane & 15) * 80 + (lane >> 4) * 16;
    const uint32_t b_lane = ((lane & 7) + ((lane >> 4) << 3)) * 80 + ((lane >> 3) & 1) * 16;

    for (int ch = 0; ch < NCH; ch++) {
        if (ch + 1 < NCH) { CP_WAIT1(); } else { CP_WAIT0(); }
        __syncthreads();
        if (ch + 2 < NCH) { copy_stage((ch + 2) % 3, ch + 2); CP_COMMIT(); }

        const uint32_t st = sbase + (ch % 3) * G_STAGE;
        const uint32_t abase = st + (wm * 64) * 80 + a_lane;
        const uint32_t bbase = st + 20480 + (wn * 16) * 80 + b_lane;
#pragma unroll
        for (int ks = 0; ks < 2; ks++) {
            const int ko = ks * 32;
            uint32_t bh_[4], bl_[4];
            LDSM4(bh_, bbase + ko);
            LDSM4(bl_, bbase + ko + 5120);
#pragma unroll
            for (int mt = 0; mt < 4; mt++) {
                uint32_t ah_[4], al_[4];
                uint32_t aa = abase + mt * (16 * 80) + ko;
                LDSM4(ah_, aa);
                LDSM4(al_, aa + 10240);
#pragma unroll
                for (int tn = 0; tn < 2; tn++) {
                    MMA16816(acc[mt][tn], ah_, bh_[tn * 2], bh_[tn * 2 + 1]);
                    MMA16816(acc[mt][tn], ah_, bl_[tn * 2], bl_[tn * 2 + 1]);
                    MMA16816(acc[mt][tn], al_, bh_[tn * 2], bh_[tn * 2 + 1]);
                }
            }
        }
        __syncthreads();
    }

    // epilogue
#pragma unroll
    for (int mt = 0; mt < 4; mt++) {
        int r = bm + wm * 64 + mt * 16 + (lane >> 2);
#pragma unroll
        for (int tn = 0; tn < 2; tn++) {
            int c = bn + wn * 16 + tn * 8 + (lane & 3) * 2;
            *(float2*)&C[(size_t)r * Nseg + c]       = make_float2(acc[mt][tn][0], acc[mt][tn][1]);
            *(float2*)&C[(size_t)(r + 8) * Nseg + c] = make_float2(acc[mt][tn][2], acc[mt][tn][3]);
        }
    }
}

// ================= HMMA flash attention =================
// One CTA per (b,kvh): 64 q-rows (4 rep-heads x 16 seq) over 4096 keys, chunk 64.
// smem (bytes):
//  qh 0         ql 17408     kh 34816     kl 52224    vh 69632    vl 87040   ([64][136] bf16, 272B rows)
//  Ss 104448 ([64][72] f32)  ph 122880  pl 132096 ([64][72] bf16, 144B rows)
//  Kr 141312  Vr 175104 ([64][132] f32 raw, 528B rows)   rowM/L/C 208896
#define ATTN_SMEM 209664

__global__ __launch_bounds__(256, 1) void attn_kernel(const float* __restrict__ cacheK,
                                                      const float* __restrict__ cacheV,
                                                      const int* __restrict__ spp)
{
    extern __shared__ char sm[];
    char*  qh = sm;
    char*  kh = sm + 34816;
    char*  vh = sm + 69632;
    float* Ss = (float*)(sm + 104448);
    char*  ph = sm + 122880;
    float* Kr = (float*)(sm + 141312);
    float* Vr = (float*)(sm + 175104);
    float* rowM = (float*)(sm + 208896);
    float* rowL = rowM + 64;
    float* rowC = rowM + 128;

    const int t = threadIdx.x, w = t >> 5, lane = t & 31;
    const int b = blockIdx.x >> 3, kvh = blockIdx.x & 7;
    const int sp = *spp;
    const int wq = w >> 2, wn = w & 3;          // 2 m-warps x 4 n-warps

    const uint32_t u_qh = smem_u32(qh), u_kh = smem_u32(kh), u_vh = smem_u32(vh);
    const uint32_t u_ph = smem_u32(ph);

    // prefetch K/V chunk via cp.async into raw fp32 staging
    auto prefetch = [&](int chunk) {
        const int t0 = chunk * 64;
#pragma unroll
        for (int j = 0; j < 16; j++) {
            int idx = j * 256 + t;
            int tensor = idx >> 11;
            int i = idx & 2047;
            int r = i >> 5, c = i & 31;          // row, 16B-chunk (4 floats)
            int tk = t0 + r;
            const float* src;
            if (tensor == 0)
                src = (tk < sp)
                    ? cacheK + (((size_t)b * MAXS + tk) * KVH + kvh) * HDIM + c * 4
                    : g_Kn + (((size_t)b * SS + (tk - sp)) * KVH + kvh) * HDIM + c * 4;
            else
                src = (tk < sp)
                    ? cacheV + (((size_t)b * MAXS + tk) * KVH + kvh) * HDIM + c * 4
                    : g_Vn + (((size_t)b * SS + (tk - sp)) * KVH + kvh) * HDIM + c * 4;
            uint32_t dst = smem_u32((tensor ? (char*)Vr : (char*)Kr) + r * 528 + c * 16);
            CP16(dst, src);
        }
    };

    prefetch(0); CP_COMMIT();

    // Q load + hi/lo convert into smem
#pragma unroll
    for (int j = 0; j < 8; j++) {
        int idx = j * 256 + t;
        int r = idx >> 5, c4 = idx & 31;
        const float4 v = *(const float4*)(g_Q +
            (((size_t)b * SS + (r & 15)) * HH + kvh * 4 + (r >> 4)) * HDIM + c4 * 4);
        bf162 h01, h23, l01, l23;
        cvt_hilo4(v, h01, h23, l01, l23);
        char* hp = qh + r * 272 + c4 * 8;
        *(bf162*)(hp)             = h01;  *(bf162*)(hp + 4)             = h23;
        *(bf162*)(hp + 17408)     = l01;  *(bf162*)(hp + 17408 + 4)     = l23;
    }
    if (t < 64) { rowM[t] = __int_as_float(0xff800000); rowL[t] = 0.f; }

    float oacc[2][4][4];
#pragma unroll
    for (int a = 0; a < 2; a++)
#pragma unroll
        for (int bq = 0; bq < 4; bq++)
#pragma unroll
            for (int cix = 0; cix < 4; cix++) oacc[a][bq][cix] = 0.f;

    const float scale = 0.08838834764831845f;   // 1/sqrt(128)
    const uint32_t a_lane = (lane & 15) * 272 + (lane >> 4) * 16;
    const uint32_t b_lane = ((lane & 7) + ((lane >> 4) << 3)) * 272 + ((lane >> 3) & 1) * 16;

    for (int ch = 0; ch < KVLEN / 64; ch++) {
        CP_WAIT0();
        __syncthreads();   // raw ready everywhere; prior chunk's smem reads done

        // convert raw K/V -> bf16 hi/lo smem
#pragma unroll
        for (int j = 0; j < 16; j++) {
            int idx = j * 256 + t;
            int tensor = idx >> 11;
            int i = idx & 2047;
            int r = i >> 5, c4 = i & 31;
            float4 v = *(const float4*)((tensor ? (char*)Vr : (char*)Kr) + r * 528 + c4 * 16);
            bf162 h01, h23, l01, l23;
            cvt_hilo4(v, h01, h23, l01, l23);
            char* hp = (tensor ? vh : kh) + r * 272 + c4 * 8;
            *(bf162*)(hp)         = h01;  *(bf162*)(hp + 4)         = h23;
            *(bf162*)(hp + 17408) = l01;  *(bf162*)(hp + 17408 + 4) = l23;
        }
        __syncthreads();   // converted tiles visible; raw free for next prefetch

        if (ch + 1 < KVLEN / 64) { prefetch(ch + 1); CP_COMMIT(); }

        // ---- S = Q K^T (3-pass hi/lo): warp tile m32 x n16 ----
        float sacc[2][2][4];
#pragma unroll
        for (int a = 0; a < 2; a++)
#pragma unroll
            for (int bq = 0; bq < 2; bq++)
#pragma unroll
                for (int cix = 0; cix < 4; cix++) sacc[a][bq][cix] = 0.f;

        const uint32_t sb_base = u_kh + (wn * 16) * 272 + b_lane;
#pragma unroll
        for (int ks = 0; ks < 8; ks++) {
            const int ko = ks * 32;
            uint32_t bh_[4], bl_[4];
            LDSM4(bh_, sb_base + ko);
            LDSM4(bl_, sb_base + ko + 17408);
#pragma unroll
            for (int mt = 0; mt < 2; mt++) {
                uint32_t aa = u_qh + (wq * 32 + mt * 16) * 272 + a_lane + ko;
                uint32_t ah_[4], al_[4];
                LDSM4(ah_, aa);
                LDSM4(al_, aa + 17408);
#pragma unroll
                for (int tn = 0; tn < 2; tn++) {
                    MMA16816(sacc[mt][tn], ah_, bh_[tn * 2], bh_[tn * 2 + 1]);
                    MMA16816(sacc[mt][tn], ah_, bl_[tn * 2], bl_[tn * 2 + 1]);
                    MMA16816(sacc[mt][tn], al_, bh_[tn * 2], bh_[tn * 2 + 1]);
                }
            }
        }
        // write scaled scores
#pragma unroll
        for (int mt = 0; mt < 2; mt++) {
            int r0 = wq * 32 + mt * 16 + (lane >> 2);
#pragma unroll
            for (int tn = 0; tn < 2; tn++) {
                int c0 = wn * 16 + tn * 8 + (lane & 3) * 2;
                *(float2*)&Ss[r0 * 72 + c0] =
                    make_float2(sacc[mt][tn][0] * scale, sacc[mt][tn][1] * scale);
                *(float2*)&Ss[(r0 + 8) * 72 + c0] =
                    make_float2(sacc[mt][tn][2] * scale, sacc[mt][tn][3] * scale);
            }
        }
        __syncthreads();

        // ---- online softmax: warp w handles rows w*8..w*8+7 ----
#pragma unroll
        for (int rr = 0; rr < 8; rr++) {
            int r = w * 8 + rr;
            float v0 = Ss[r * 72 + lane], v1 = Ss[r * 72 + 32 + lane];
            float mx = fmaxf(v0, v1);
#pragma unroll
            for (int o = 16; o; o >>= 1) mx = fmaxf(mx, __shfl_xor_sync(0xffffffffu, mx, o));
            float mo = rowM[r];
            float m  = fmaxf(mo, mx);
            float e0 = __expf(v0 - m), e1 = __expf(v1 - m);
            float s2 = e0 + e1;
#pragma unroll
            for (int o = 16; o; o >>= 1) s2 += __shfl_xor_sync(0xffffffffu, s2, o);
            if (lane == 0) {
                float corr = __expf(mo - m);
                rowC[r] = corr; rowM[r] = m; rowL[r] = rowL[r] * corr + s2;
            }
            bf16 h0 = __float2bfloat16(e0);
            bf16 h1 = __float2bfloat16(e1);
            ((bf16*)ph)[r * 72 + lane]              = h0;
            ((bf16*)ph)[r * 72 + 32 + lane]         = h1;
            ((bf16*)(ph + 9216))[r * 72 + lane]      = __float2bfloat16(e0 - __bfloat162float(h0));
            ((bf16*)(ph + 9216))[r * 72 + 32 + lane] = __float2bfloat16(e1 - __bfloat162float(h1));
        }
        __syncthreads();

        // ---- rescale O, then O += P V (3-pass hi/lo): warp tile m32 x n32 ----
#pragma unroll
        for (int mt = 0; mt < 2; mt++) {
            int rbase = wq * 32 + mt * 16 + (lane >> 2);
            float ca = rowC[rbase], cb = rowC[rbase + 8];
#pragma unroll
            for (int tn = 0; tn < 4; tn++) {
                oacc[mt][tn][0] *= ca; oacc[mt][tn][1] *= ca;
                oacc[mt][tn][2] *= cb; oacc[mt][tn][3] *= cb;
            }
        }
#pragma unroll
        for (int ks = 0; ks < 4; ks++) {
            uint32_t vbh[2][4], vbl[2][4];
#pragma unroll
            for (int dt = 0; dt < 2; dt++) {
                uint32_t va = u_vh + (ks * 16 + (lane & 15)) * 272 +
                              (wn * 32 + dt * 16 + (lane >> 4) * 8) * 2;
                LDSM4T(vbh[dt], va);
                LDSM4T(vbl[dt], va + 17408);
            }
#pragma unroll
            for (int mt = 0; mt < 2; mt++) {
                uint32_t pa = u_ph + (wq * 32 + mt * 16 + (lane & 15)) * 144 +
                              ks * 32 + (lane >> 4) * 16;
                uint32_t ph_[4], pl_[4];
                LDSM4(ph_, pa);
                LDSM4(pl_, pa + 9216);
#pragma unroll
                for (int tn = 0; tn < 4; tn++) {
                    int dt = tn >> 1, pr = (tn & 1) * 2;
                    MMA16816(oacc[mt][tn], ph_, vbh[dt][pr], vbh[dt][pr + 1]);
                    MMA16816(oacc[mt][tn], ph_, vbl[dt][pr], vbl[dt][pr + 1]);
                    MMA16816(oacc[mt][tn], pl_, vbh[dt][pr], vbh[dt][pr + 1]);
                }
            }
        }
    }

    // ---- normalize + write ctx as bf16 hi/lo ----
#pragma unroll
    for (int mt = 0; mt < 2; mt++) {
        int ra = wq * 32 + mt * 16 + (lane >> 2);
        int rb = ra + 8;
        float ia = 1.f / rowL[ra], ib = 1.f / rowL[rb];
#pragma unroll
        for (int tn = 0; tn < 4; tn++) {
            int col = wn * 32 + tn * 8 + (lane & 3) * 2;
            float va0 = oacc[mt][tn][0] * ia, va1 = oacc[mt][tn][1] * ia;
            float vb0 = oacc[mt][tn][2] * ib, vb1 = oacc[mt][tn][3] * ib;
            size_t oa = (((size_t)b * SS + (ra & 15)) * HH + kvh * 4 + (ra >> 4)) * HDIM + col;
            size_t ob = (((size_t)b * SS + (rb & 15)) * HH + kvh * 4 + (rb >> 4)) * HDIM + col;
            bf162 ha, la, hb, lb;
            ha.x = __float2bfloat16(va0); ha.y = __float2bfloat16(va1);
            la.x = __float2bfloat16(va0 - __bfloat162float(ha.x));
            la.y = __float2bfloat16(va1 - __bfloat162float(ha.y));
            hb.x = __float2bfloat16(vb0); hb.y = __float2bfloat16(vb1);
            lb.x = __float2bfloat16(vb0 - __bfloat162float(hb.x));
            lb.y = __float2bfloat16(vb1 - __bfloat162float(hb.y));
            *(bf162*)&g_Chi[oa] = ha; *(bf162*)&g_Clo[oa] = la;
            *(bf162*)&g_Chi[ob] = hb; *(bf162*)&g_Clo[ob] = lb;
        }
    }
}

// ---------------- launch ----------------
extern "C" void kernel_launch(void* const* d_in, const int* in_sizes, int n_in,
                              void* d_out, int out_size)
{
    const float* x      = (const float*)d_in[0];
    const float* Wq     = (const float*)d_in[1];
    const float* Wk     = (const float*)d_in[2];
    const float* Wv     = (const float*)d_in[3];
    const float* Wo     = (const float*)d_in[4];
    const float* cacheK = (const float*)d_in[5];
    const float* cacheV = (const float*)d_in[6];
    const int*   spp    = (const int*)  d_in[7];
    float*       out    = (float*)d_out;
    (void)in_sizes; (void)n_in; (void)out_size;

    void *xh, *xl, *ch, *cl, *qth, *qtl, *kth, *ktl, *vth, *vtl, *oth, *otl;
    void *qp, *kp, *vp;
    cudaGetSymbolAddress(&xh,  g_Xhi);  cudaGetSymbolAddress(&xl,  g_Xlo);
    cudaGetSymbolAddress(&ch,  g_Chi);  cudaGetSymbolAddress(&cl,  g_Clo);
    cudaGetSymbolAddress(&qth, g_WqTh); cudaGetSymbolAddress(&qtl, g_WqTl);
    cudaGetSymbolAddress(&kth, g_WkTh); cudaGetSymbolAddress(&ktl, g_WkTl);
    cudaGetSymbolAddress(&vth, g_WvTh); cudaGetSymbolAddress(&vtl, g_WvTl);
    cudaGetSymbolAddress(&oth, g_WoTh); cudaGetSymbolAddress(&otl, g_WoTl);
    cudaGetSymbolAddress(&qp,  g_Q);    cudaGetSymbolAddress(&kp,  g_Kn);
    cudaGetSymbolAddress(&vp,  g_Vn);

    cudaFuncSetAttribute(hgemm, cudaFuncAttributeMaxDynamicSharedMemorySize, G_SMEM);
    cudaFuncSetAttribute(attn_kernel, cudaFuncAttributeMaxDynamicSharedMemorySize, ATTN_SMEM);

    dim3 blk(256);
    // weight/activation conversion
    convT<<<dim3(64, 64), blk>>>(Wq, (bf16*)qth, (bf16*)qtl, 4096, 4096);
    convT<<<dim3(16, 64), blk>>>(Wk, (bf16*)kth, (bf16*)ktl, 4096, 1024);
    convT<<<dim3(16, 64), blk>>>(Wv, (bf16*)vth, (bf16*)vtl, 4096, 1024);
    convT<<<dim3(64, 64), blk>>>(Wo, (bf16*)oth, (bf16*)otl, 4096, 4096);
    conv_hilo<<<4096, 256>>>(x, (bf16*)xh, (bf16*)xl, MROWS * DK);

    // fused QKV projection (96 n-tiles x 2 m-tiles = 192 CTAs)
    hgemm<<<dim3(96, 2), blk, G_SMEM>>>(
        (bf16*)xh, (bf16*)xl,
        (bf16*)qth, (bf16*)qtl, (float*)qp, 4096,
        (bf16*)kth, (bf16*)ktl, (float*)kp, 1024,
        (bf16*)vth, (bf16*)vtl, (float*)vp, 1024);

    // RoPE on Q and new K
    {
        int total = MROWS * HH * 64 + MROWS * KVH * 64;
        rope_kernel<<<(total + 255) / 256, 256>>>(spp);
    }

    // attention -> g_Chi/g_Clo
    attn_kernel<<<BB * KVH, blk, ATTN_SMEM>>>(cacheK, cacheV, spp);

    // output projection
    hgemm<<<dim3(64, 2), blk, G_SMEM>>>(
        (bf16*)ch, (bf16*)cl,
        (bf16*)oth, (bf16*)otl, out, 4096,
        (const bf16*)0, (const bf16*)0, (float*)0, 0,
        (const bf16*)0, (const bf16*)0, (float*)0, 0);
}

// round 6
// speedup vs baseline: 3.0985x; 1.1584x over previous
#include <cuda_runtime.h>
#include <cuda_bf16.h>
#include <math.h>
#include <stdint.h>

// ---------------- problem constants ----------------
#define BB    16
#define SS    16
#define HH    32
#define KVH   8
#define HDIM  128
#define MAXS  4096
#define MROWS 256
#define DK    4096
#define KVLEN 4096

typedef __nv_bfloat16  bf16;
typedef __nv_bfloat162 bf162;

// ---------------- device scratch ----------------
__device__ bf16  g_Xhi[MROWS * DK], g_Xlo[MROWS * DK];
__device__ bf16  g_Chi[MROWS * DK], g_Clo[MROWS * DK];
__device__ float g_Q [MROWS * 4096];
__device__ float g_Kn[MROWS * 1024];
__device__ float g_Vn[MROWS * 1024];
__device__ float g_pM[2 * 128 * 64], g_pL[2 * 128 * 64];
__device__ float g_pC[2 * 128 * 64 * 128];

// ---------------- PTX helpers (baseline ISA only — no tcgen05 on compute_103) ----------------
__device__ __forceinline__ uint32_t smem_u32(const void* p) {
    uint32_t a;
    asm("{ .reg .u64 t; cvta.to.shared.u64 t, %1; cvt.u32.u64 %0, t; }" : "=r"(a) : "l"(p));
    return a;
}
#define LDSM4(r, addr) \
    asm volatile("ldmatrix.sync.aligned.m8n8.x4.shared.b16 {%0,%1,%2,%3}, [%4];" \
        : "=r"((r)[0]), "=r"((r)[1]), "=r"((r)[2]), "=r"((r)[3]) : "r"(addr))
#define LDSM2(r, addr) \
    asm volatile("ldmatrix.sync.aligned.m8n8.x2.shared.b16 {%0,%1}, [%2];" \
        : "=r"((r)[0]), "=r"((r)[1]) : "r"(addr))
#define LDSM4T(r, addr) \
    asm volatile("ldmatrix.sync.aligned.m8n8.x4.trans.shared.b16 {%0,%1,%2,%3}, [%4];" \
        : "=r"((r)[0]), "=r"((r)[1]), "=r"((r)[2]), "=r"((r)[3]) : "r"(addr))
#define MMA16816(d, a, b0, b1) \
    asm volatile("mma.sync.aligned.m16n8k16.row.col.f32.bf16.bf16.f32 " \
        "{%0,%1,%2,%3}, {%4,%5,%6,%7}, {%8,%9}, {%0,%1,%2,%3};" \
        : "+f"((d)[0]), "+f"((d)[1]), "+f"((d)[2]), "+f"((d)[3]) \
        : "r"((a)[0]), "r"((a)[1]), "r"((a)[2]), "r"((a)[3]), "r"(b0), "r"(b1))
#define CP16(dst, src) \
    asm volatile("cp.async.cg.shared.global [%0], [%1], 16;" :: "r"(dst), "l"(src))
#define CP_COMMIT() asm volatile("cp.async.commit_group;" ::: "memory")
#define CP_WAIT0()  asm volatile("cp.async.wait_group 0;" ::: "memory")
#define CP_WAIT1()  asm volatile("cp.async.wait_group 1;" ::: "memory")

__device__ __forceinline__ void cvt_hilo4(float4 v, bf162& h01, bf162& h23,
                                          bf162& l01, bf162& l23) {
    h01.x = __float2bfloat16(v.x); h01.y = __float2bfloat16(v.y);
    h23.x = __float2bfloat16(v.z); h23.y = __float2bfloat16(v.w);
    l01.x = __float2bfloat16(v.x - __bfloat162float(h01.x));
    l01.y = __float2bfloat16(v.y - __bfloat162float(h01.y));
    l23.x = __float2bfloat16(v.z - __bfloat162float(h23.x));
    l23.y = __float2bfloat16(v.w - __bfloat162float(h23.y));
}

// ---------------- x hi/lo conversion ----------------
__global__ void conv_hilo(const float* __restrict__ in, bf16* __restrict__ hi,
                          bf16* __restrict__ lo, int n)
{
    int i = blockIdx.x * blockDim.x + threadIdx.x;
    if (i >= n) return;
    float v = in[i];
    bf16 h = __float2bfloat16(v);
    hi[i] = h;
    lo[i] = __float2bfloat16(v - __bfloat162float(h));
}

// ---------------- RoPE (in place on g_Q and g_Kn) ----------------
__global__ void rope_kernel(const int* __restrict__ spp)
{
    const int nq = MROWS * HH  * (HDIM / 2);
    const int nk = MROWS * KVH * (HDIM / 2);
    int idx = blockIdx.x * blockDim.x + threadIdx.x;
    if (idx >= nq + nk) return;
    const int sp = *spp;

    float* buf; int nh; int i;
    if (idx < nq) { buf = g_Q;  nh = HH;  i = idx; }
    else          { buf = g_Kn; nh = KVH; i = idx - nq; }

    const int j = i & 63;
    const int h = (i >> 6) % nh;
    const int m = i / (64 * nh);
    const int s = m & (SS - 1);

    float p     = (float)(sp + s);
    float theta = powf(10000.0f, -(float)(2 * j) / 128.0f);
    float f     = p * theta;
    float sn, c;
    sincosf(f, &sn, &c);

    float* ptr = buf + ((size_t)m * nh + h) * HDIM + (j << 1);
    float xr = ptr[0], xi = ptr[1];
    ptr[0] = xr * c - xi * sn;
    ptr[1] = xr * sn + xi * c;
}

// ================= HMMA hi/lo GEMM with fused fp32-weight conversion =================
// C = A[256,4096] @ W[4096,N], tile 128x64, chunk K=32, 3-stage cp.async pipeline.
// A comes pre-split bf16 hi/lo; W is raw fp32, staged + converted in-kernel.
// stage: Ahi[128][80B] (10240) | Alo (10240) | Wraw[32][272B] (8704) = 29184
// after 3 stages: convBhi[32][144B] (4608) | convBlo (4608)
#define G_STAGE 29184
#define G_CONV  (3 * G_STAGE)
#define G_SMEM  (G_CONV + 9216)

__global__ __launch_bounds__(256, 2) void hgemm(
    const bf16* __restrict__ Ah, const bf16* __restrict__ Al,
    const float* __restrict__ W0, float* __restrict__ C0, int N0,
    const float* __restrict__ W1, float* __restrict__ C1, int N1,
    const float* __restrict__ W2, float* __restrict__ C2, int N2)
{
    extern __shared__ char smg[];
    const int t = threadIdx.x, w = t >> 5, lane = t & 31;
    const int wm = w >> 2, wn = w & 3;          // 2 m-warps x 4 n-warps
    const int bm = blockIdx.y * 128;

    // segment select
    int xt = blockIdx.x;
    const int t0n = N0 >> 6, t1n = N1 >> 6;
    const float* W; float* C; int Nseg, bn;
    if (xt < t0n)            { W = W0; C = C0; Nseg = N0; bn = xt * 64; }
    else if (xt < t0n + t1n) { W = W1; C = C1; Nseg = N1; bn = (xt - t0n) * 64; }
    else                     { W = W2; C = C2; Nseg = N2; bn = (xt - t0n - t1n) * 64; }

    const uint32_t sbase = smem_u32(smg);
    const uint32_t cvh = sbase + G_CONV;        // converted B hi
    const uint32_t cvl = cvh + 4608;            // converted B lo

    // stage copier: A hi/lo bf16 (1024 cp16) + W fp32 raw (512 cp16) = 6/thread
    auto copy_stage = [&](int slot, int ch) {
        const int k0 = ch * 32;
        char* base = smg + slot * G_STAGE;
#pragma unroll
        for (int j = 0; j < 6; j++) {
            int idx = j * 256 + t;
            if (idx < 1024) {
                int hl = idx >> 9, i = idx & 511, r = i >> 2, c = i & 3;
                const bf16* src = (hl ? Al : Ah) + (size_t)(bm + r) * DK + k0 + c * 8;
                CP16(smem_u32(base + hl * 10240 + r * 80 + c * 16), src);
            } else {
                int q = idx - 1024, r = q >> 4, c = q & 15;  // 32 k-rows x 16 f4-cols
                const float* src = W + (size_t)(k0 + r) * Nseg + bn + c * 4;
                CP16(smem_u32(base + 20480 + r * 272 + c * 16), src);
            }
        }
    };

    float acc[4][2][4];
#pragma unroll
    for (int a = 0; a < 4; a++)
#pragma unroll
        for (int bq = 0; bq < 2; bq++)
#pragma unroll
            for (int cix = 0; cix < 4; cix++) acc[a][bq][cix] = 0.f;

    const int NCH = DK / 32;       // 128
    copy_stage(0, 0); CP_COMMIT();
    copy_stage(1, 1); CP_COMMIT();

    const uint32_t a_lane = (lane & 15) * 80 + (lane >> 4) * 16;
    const uint32_t bT_lane = (lane & 15) * 144 + (lane >> 4) * 16;

    for (int ch = 0; ch < NCH; ch++) {
        if (ch + 1 < NCH) { CP_WAIT1(); } else { CP_WAIT0(); }
        __syncthreads();            // raw ready; prior MMAs done -> convB reusable

        // convert W raw fp32 -> bf16 hi/lo (512 f4, 2 per thread)
        {
            char* raw = smg + (ch % 3) * G_STAGE + 20480;
#pragma unroll
            for (int j = 0; j < 2; j++) {
                int e = j * 256 + t;
                int r = e >> 4, c4 = e & 15;
                float4 v = *(const float4*)(raw + r * 272 + c4 * 16);
                bf162 h01, h23, l01, l23;
                cvt_hilo4(v, h01, h23, l01, l23);
                char* hp = smg + G_CONV + r * 144 + c4 * 8;
                *(bf162*)(hp)            = h01;  *(bf162*)(hp + 4)            = h23;
                *(bf162*)(hp + 4608)     = l01;  *(bf162*)(hp + 4608 + 4)     = l23;
            }
        }
        __syncthreads();            // convB visible

        if (ch + 2 < NCH) { copy_stage((ch + 2) % 3, ch + 2); CP_COMMIT(); }

        const uint32_t st = sbase + (ch % 3) * G_STAGE;
        const uint32_t abase = st + (wm * 64) * 80 + a_lane;
#pragma unroll
        for (int ks = 0; ks < 2; ks++) {
            uint32_t ba = cvh + ks * 16 * 144 + bT_lane + wn * 32;
            uint32_t bh_[4], bl_[4];
            LDSM4T(bh_, ba);
            LDSM4T(bl_, ba + 4608);
#pragma unroll
            for (int mt = 0; mt < 4; mt++) {
                uint32_t ah_[4], al_[4];
                uint32_t aa = abase + mt * (16 * 80) + ks * 32;
                LDSM4(ah_, aa);
                LDSM4(al_, aa + 10240);
#pragma unroll
                for (int tn = 0; tn < 2; tn++) {
                    MMA16816(acc[mt][tn], ah_, bh_[tn * 2], bh_[tn * 2 + 1]);
                    MMA16816(acc[mt][tn], ah_, bl_[tn * 2], bl_[tn * 2 + 1]);
                    MMA16816(acc[mt][tn], al_, bh_[tn * 2], bh_[tn * 2 + 1]);
                }
            }
        }
    }

    // epilogue
#pragma unroll
    for (int mt = 0; mt < 4; mt++) {
        int r = bm + wm * 64 + mt * 16 + (lane >> 2);
#pragma unroll
        for (int tn = 0; tn < 2; tn++) {
            int c = bn + wn * 16 + tn * 8 + (lane & 3) * 2;
            *(float2*)&C[(size_t)r * Nseg + c]       = make_float2(acc[mt][tn][0], acc[mt][tn][1]);
            *(float2*)&C[(size_t)(r + 8) * Nseg + c] = make_float2(acc[mt][tn][2], acc[mt][tn][3]);
        }
    }
}

// ================= HMMA flash attention, KV split in 2, 2 CTAs/SM =================
// CTA = (b,kvh,half): 64 q-rows over 2048 keys, chunk 32, register-staged KV loads.
// smem layout (bytes):
#define AT_QH 0          // [64][272]  17408 (hi), lo at +17408
#define AT_KH 34816      // [32][272]   8704 (hi), lo at +8704
#define AT_VH 52224      // [32][272]   8704 (hi), lo at +8704
#define AT_SS 69632      // [64][40] f32  10240
#define AT_PH 79872      // [64][80B] bf16 5120 (hi), lo at +5120
#define AT_RM 90112      // rowM/L/C 3*64 f32
#define ATTN_SMEM 90880
#define NCHUNK 64        // 2048 / 32

__global__ __launch_bounds__(256, 2) void attn_kernel(const float* __restrict__ cacheK,
                                                      const float* __restrict__ cacheV,
                                                      const int* __restrict__ spp,
                                                      float* __restrict__ pM,
                                                      float* __restrict__ pL,
                                                      float* __restrict__ pC)
{
    extern __shared__ char sm[];
    char*  qh = sm + AT_QH;
    char*  kh = sm + AT_KH;
    char*  vh = sm + AT_VH;
    float* Ss = (float*)(sm + AT_SS);
    char*  ph = sm + AT_PH;
    float* rowM = (float*)(sm + AT_RM);
    float* rowL = rowM + 64;
    float* rowC = rowM + 128;

    const int t = threadIdx.x, w = t >> 5, lane = t & 31;
    const int b = blockIdx.x >> 3, kvh = blockIdx.x & 7;
    const int half = blockIdx.y;
    const int pb = half * 128 + blockIdx.x;
    const int kvb = half * 2048;
    const int sp = *spp;
    const int wq = w >> 2, wn = w & 3;          // 2 m-warps x 4 n-warps

    const uint32_t u_qh = smem_u32(qh), u_kh = smem_u32(kh), u_vh = smem_u32(vh);
    const uint32_t u_ph = smem_u32(ph);

    // per-thread KV register staging: 4 f4 of K + 4 f4 of V per chunk
    float4 kReg[4], vReg[4];
    auto load_kv = [&](int chunk) {
        const int t0 = kvb + chunk * 32;
#pragma unroll
        for (int j = 0; j < 4; j++) {
            int e = j * 256 + t;
            int r = e >> 5, c4 = e & 31;
            int tk = t0 + r;
            const float* ks = (tk < sp)
                ? cacheK + (((size_t)b * MAXS + tk) * KVH + kvh) * HDIM + c4 * 4
                : g_Kn + (((size_t)b * SS + (tk - sp)) * KVH + kvh) * HDIM + c4 * 4;
            const float* vs = (tk < sp)
                ? cacheV + (((size_t)b * MAXS + tk) * KVH + kvh) * HDIM + c4 * 4
                : g_Vn + (((size_t)b * SS + (tk - sp)) * KVH + kvh) * HDIM + c4 * 4;
            kReg[j] = *(const float4*)ks;
            vReg[j] = *(const float4*)vs;
        }
    };

    load_kv(0);

    // Q load + hi/lo convert into smem
#pragma unroll
    for (int j = 0; j < 8; j++) {
        int idx = j * 256 + t;
        int r = idx >> 5, c4 = idx & 31;
        const float4 v = *(const float4*)(g_Q +
            (((size_t)b * SS + (r & 15)) * HH + kvh * 4 + (r >> 4)) * HDIM + c4 * 4);
        bf162 h01, h23, l01, l23;
        cvt_hilo4(v, h01, h23, l01, l23);
        char* hp = qh + r * 272 + c4 * 8;
        *(bf162*)(hp)         = h01;  *(bf162*)(hp + 4)         = h23;
        *(bf162*)(hp + 17408) = l01;  *(bf162*)(hp + 17408 + 4) = l23;
    }
    if (t < 64) { rowM[t] = __int_as_float(0xff800000); rowL[t] = 0.f; }

    float oacc[2][4][4];
#pragma unroll
    for (int a = 0; a < 2; a++)
#pragma unroll
        for (int bq = 0; bq < 4; bq++)
#pragma unroll
            for (int cix = 0; cix < 4; cix++) oacc[a][bq][cix] = 0.f;

    const float scale = 0.08838834764831845f;   // 1/sqrt(128)
    const uint32_t a_lane = (lane & 15) * 272 + (lane >> 4) * 16;

    for (int ch = 0; ch < NCHUNK; ch++) {
        __syncthreads();    // prior MMAs done reading kh/vh

        // deposit staged regs as bf16 hi/lo
#pragma unroll
        for (int j = 0; j < 4; j++) {
            int e = j * 256 + t;
            int r = e >> 5, c4 = e & 31;
            bf162 h01, h23, l01, l23;
            cvt_hilo4(kReg[j], h01, h23, l01, l23);
            char* hp = kh + r * 272 + c4 * 8;
            *(bf162*)(hp)        = h01;  *(bf162*)(hp + 4)        = h23;
            *(bf162*)(hp + 8704) = l01;  *(bf162*)(hp + 8704 + 4) = l23;
            cvt_hilo4(vReg[j], h01, h23, l01, l23);
            hp = vh + r * 272 + c4 * 8;
            *(bf162*)(hp)        = h01;  *(bf162*)(hp + 4)        = h23;
            *(bf162*)(hp + 8704) = l01;  *(bf162*)(hp + 8704 + 4) = l23;
        }
        __syncthreads();

        if (ch + 1 < NCHUNK) load_kv(ch + 1);   // LDG latency hidden by MMA phase

        // ---- S = Q K^T (3-pass hi/lo): warp tile m32 x n8 ----
        float sacc[2][4];
#pragma unroll
        for (int a = 0; a < 2; a++)
#pragma unroll
            for (int cix = 0; cix < 4; cix++) sacc[a][cix] = 0.f;

#pragma unroll
        for (int ks = 0; ks < 8; ks++) {
            const int ko = ks * 32;
            uint32_t ba = u_kh + (wn * 8 + (lane & 7)) * 272 + ko + ((lane >> 3) & 1) * 16;
            uint32_t bh_[2], bl_[2];
            LDSM2(bh_, ba);
            LDSM2(bl_, ba + 8704);
#pragma unroll
            for (int mt = 0; mt < 2; mt++) {
                uint32_t aa = u_qh + (wq * 32 + mt * 16) * 272 + a_lane + ko;
                uint32_t ah_[4], al_[4];
                LDSM4(ah_, aa);
                LDSM4(al_, aa + 17408);
                MMA16816(sacc[mt], ah_, bh_[0], bh_[1]);
                MMA16816(sacc[mt], ah_, bl_[0], bl_[1]);
                MMA16816(sacc[mt], al_, bh_[0], bh_[1]);
            }
        }
#pragma unroll
        for (int mt = 0; mt < 2; mt++) {
            int r0 = wq * 32 + mt * 16 + (lane >> 2);
            int c0 = wn * 8 + (lane & 3) * 2;
            *(float2*)&Ss[r0 * 40 + c0]       = make_float2(sacc[mt][0] * scale, sacc[mt][1] * scale);
            *(float2*)&Ss[(r0 + 8) * 40 + c0] = make_float2(sacc[mt][2] * scale, sacc[mt][3] * scale);
        }
        __syncthreads();

        // ---- online softmax: warp w rows w*8..w*8+7, 32 cols ----
#pragma unroll
        for (int rr = 0; rr < 8; rr++) {
            int r = w * 8 + rr;
            float v0 = Ss[r * 40 + lane];
            float mx = v0;
#pragma unroll
            for (int o = 16; o; o >>= 1) mx = fmaxf(mx, __shfl_xor_sync(0xffffffffu, mx, o));
            float mo = rowM[r];
            float m  = fmaxf(mo, mx);
            float e0 = __expf(v0 - m);
            float s2 = e0;
#pragma unroll
            for (int o = 16; o; o >>= 1) s2 += __shfl_xor_sync(0xffffffffu, s2, o);
            if (lane == 0) {
                float corr = __expf(mo - m);
                rowC[r] = corr; rowM[r] = m; rowL[r] = rowL[r] * corr + s2;
            }
            bf16 h0 = __float2bfloat16(e0);
            ((bf16*)ph)[r * 40 + lane]          = h0;
            ((bf16*)(ph + 5120))[r * 40 + lane] = __float2bfloat16(e0 - __bfloat162float(h0));
        }
        __syncthreads();

        // ---- rescale O, then O += P V (3-pass hi/lo): warp tile m32 x n32 ----
#pragma unroll
        for (int mt = 0; mt < 2; mt++) {
            int rbase = wq * 32 + mt * 16 + (lane >> 2);
            float ca = rowC[rbase], cb = rowC[rbase + 8];
#pragma unroll
            for (int tn = 0; tn < 4; tn++) {
                oacc[mt][tn][0] *= ca; oacc[mt][tn][1] *= ca;
                oacc[mt][tn][2] *= cb; oacc[mt][tn][3] *= cb;
            }
        }
#pragma unroll
        for (int ks = 0; ks < 2; ks++) {
            uint32_t vbh[2][4], vbl[2][4];
#pragma unroll
            for (int dt = 0; dt < 2; dt++) {
                uint32_t va = u_vh + (ks * 16 + (lane & 15)) * 272 +
                              (wn * 32 + dt * 16 + (lane >> 4) * 8) * 2;
                LDSM4T(vbh[dt], va);
                LDSM4T(vbl[dt], va + 8704);
            }
#pragma unroll
            for (int mt = 0; mt < 2; mt++) {
                uint32_t pa = u_ph + (wq * 32 + mt * 16 + (lane & 15)) * 80 +
                              ks * 32 + (lane >> 4) * 16;
                uint32_t ph_[4], pl_[4];
                LDSM4(ph_, pa);
                LDSM4(pl_, pa + 5120);
#pragma unroll
                for (int tn = 0; tn < 4; tn++) {
                    int dt = tn >> 1, pr = (tn & 1) * 2;
                    MMA16816(oacc[mt][tn], ph_, vbh[dt][pr], vbh[dt][pr + 1]);
                    MMA16816(oacc[mt][tn], ph_, vbl[dt][pr], vbl[dt][pr + 1]);
                    MMA16816(oacc[mt][tn], pl_, vbh[dt][pr], vbh[dt][pr + 1]);
                }
            }
        }
    }

    // ---- store unnormalized partials ----
#pragma unroll
    for (int mt = 0; mt < 2; mt++) {
        int ra = wq * 32 + mt * 16 + (lane >> 2);
        int rb = ra + 8;
#pragma unroll
        for (int tn = 0; tn < 4; tn++) {
            int col = wn * 32 + tn * 8 + (lane & 3) * 2;
            *(float2*)&pC[((size_t)pb * 64 + ra) * 128 + col] =
                make_float2(oacc[mt][tn][0], oacc[mt][tn][1]);
            *(float2*)&pC[((size_t)pb * 64 + rb) * 128 + col] =
                make_float2(oacc[mt][tn][2], oacc[mt][tn][3]);
        }
    }
    if (t < 64) {
        pM[pb * 64 + t] = rowM[t];
        pL[pb * 64 + t] = rowL[t];
    }
}

// ---------------- combine halves + convert ctx to bf16 hi/lo ----------------
__global__ void combine_kernel(const float* __restrict__ pM, const float* __restrict__ pL,
                               const float* __restrict__ pC,
                               bf16* __restrict__ Chi, bf16* __restrict__ Clo)
{
    const int bq  = blockIdx.x;          // 0..127
    const int b   = bq >> 3;
    const int kvh = bq & 7;
    const int t   = threadIdx.x;

    for (int idx = t; idx < 64 * 128; idx += 256) {
        int r = idx >> 7;
        int d = idx & 127;
        float m0 = pM[bq * 64 + r],         m1 = pM[(128 + bq) * 64 + r];
        float l0 = pL[bq * 64 + r],         l1 = pL[(128 + bq) * 64 + r];
        float m  = fmaxf(m0, m1);
        float w0 = __expf(m0 - m), w1 = __expf(m1 - m);
        float l  = l0 * w0 + l1 * w1;
        float c0 = pC[((size_t)bq * 64 + r) * 128 + d];
        float c1 = pC[((size_t)(128 + bq) * 64 + r) * 128 + d];
        float v  = (c0 * w0 + c1 * w1) / l;

        int rep = r >> 4, s = r & 15;
        size_t o = ((size_t)(b * SS + s) * HH + kvh * 4 + rep) * HDIM + d;
        bf16 hi = __float2bfloat16(v);
        Chi[o] = hi;
        Clo[o] = __float2bfloat16(v - __bfloat162float(hi));
    }
}

// ---------------- launch ----------------
extern "C" void kernel_launch(void* const* d_in, const int* in_sizes, int n_in,
                              void* d_out, int out_size)
{
    const float* x      = (const float*)d_in[0];
    const float* Wq     = (const float*)d_in[1];
    const float* Wk     = (const float*)d_in[2];
    const float* Wv     = (const float*)d_in[3];
    const float* Wo     = (const float*)d_in[4];
    const float* cacheK = (const float*)d_in[5];
    const float* cacheV = (const float*)d_in[6];
    const int*   spp    = (const int*)  d_in[7];
    float*       out    = (float*)d_out;
    (void)in_sizes; (void)n_in; (void)out_size;

    void *xh, *xl, *ch, *cl, *qp, *kp, *vp, *pm, *pl, *pc;
    cudaGetSymbolAddress(&xh, g_Xhi);  cudaGetSymbolAddress(&xl, g_Xlo);
    cudaGetSymbolAddress(&ch, g_Chi);  cudaGetSymbolAddress(&cl, g_Clo);
    cudaGetSymbolAddress(&qp, g_Q);    cudaGetSymbolAddress(&kp, g_Kn);
    cudaGetSymbolAddress(&vp, g_Vn);
    cudaGetSymbolAddress(&pm, g_pM);   cudaGetSymbolAddress(&pl, g_pL);
    cudaGetSymbolAddress(&pc, g_pC);

    cudaFuncSetAttribute(hgemm, cudaFuncAttributeMaxDynamicSharedMemorySize, G_SMEM);
    cudaFuncSetAttribute(attn_kernel, cudaFuncAttributeMaxDynamicSharedMemorySize, ATTN_SMEM);

    dim3 blk(256);
    // x hi/lo conversion (weights converted in-kernel by hgemm)
    conv_hilo<<<4096, 256>>>(x, (bf16*)xh, (bf16*)xl, MROWS * DK);

    // fused QKV projection: fp32 weights converted on the fly
    hgemm<<<dim3(96, 2), blk, G_SMEM>>>(
        (bf16*)xh, (bf16*)xl,
        Wq, (float*)qp, 4096,
        Wk, (float*)kp, 1024,
        Wv, (float*)vp, 1024);

    // RoPE on Q and new K
    {
        int total = MROWS * HH * 64 + MROWS * KVH * 64;
        rope_kernel<<<(total + 255) / 256, 256>>>(spp);
    }

    // attention (KV split in 2, 2 CTAs/SM) + combine -> g_Chi/g_Clo
    attn_kernel<<<dim3(128, 2), blk, ATTN_SMEM>>>(cacheK, cacheV, spp,
                                                  (float*)pm, (float*)pl, (float*)pc);
    combine_kernel<<<128, blk>>>((float*)pm, (float*)pl, (float*)pc,
                                 (bf16*)ch, (bf16*)cl);

    // output projection
    hgemm<<<dim3(64, 2), blk, G_SMEM>>>(
        (bf16*)ch, (bf16*)cl,
        Wo, out, 4096,
        (const float*)0, (float*)0, 0,
        (const float*)0, (float*)0, 0);
}

// round 8
// speedup vs baseline: 3.6512x; 1.1784x over previous
#include <cuda_runtime.h>
#include <cuda_bf16.h>
#include <math.h>
#include <stdint.h>

// ---------------- problem constants ----------------
#define BB    16
#define SS    16
#define HH    32
#define KVH   8
#define HDIM  128
#define MAXS  4096
#define MROWS 256
#define DK    4096
#define KVLEN 4096

typedef __nv_bfloat16  bf16;
typedef __nv_bfloat162 bf162;

// ---------------- device scratch ----------------
__device__ bf16  g_Xhi[MROWS * DK], g_Xlo[MROWS * DK];
__device__ bf16  g_Chi[MROWS * DK], g_Clo[MROWS * DK];
__device__ float g_Q [MROWS * 4096];
__device__ float g_Kn[MROWS * 1024];
__device__ float g_Vn[MROWS * 1024];
__device__ float g_pM[2 * 128 * 64], g_pL[2 * 128 * 64];
__device__ float g_pC[2 * 128 * 64 * 128];

// ---------------- PTX helpers (baseline ISA only — no tcgen05 on compute_103) ----------------
__device__ __forceinline__ uint32_t smem_u32(const void* p) {
    uint32_t a;
    asm("{ .reg .u64 t; cvta.to.shared.u64 t, %1; cvt.u32.u64 %0, t; }" : "=r"(a) : "l"(p));
    return a;
}
#define LDSM4(r, addr) \
    asm volatile("ldmatrix.sync.aligned.m8n8.x4.shared.b16 {%0,%1,%2,%3}, [%4];" \
        : "=r"((r)[0]), "=r"((r)[1]), "=r"((r)[2]), "=r"((r)[3]) : "r"(addr))
#define LDSM4T(r, addr) \
    asm volatile("ldmatrix.sync.aligned.m8n8.x4.trans.shared.b16 {%0,%1,%2,%3}, [%4];" \
        : "=r"((r)[0]), "=r"((r)[1]), "=r"((r)[2]), "=r"((r)[3]) : "r"(addr))
#define MMA16816(d, a, b0, b1) \
    asm volatile("mma.sync.aligned.m16n8k16.row.col.f32.bf16.bf16.f32 " \
        "{%0,%1,%2,%3}, {%4,%5,%6,%7}, {%8,%9}, {%0,%1,%2,%3};" \
        : "+f"((d)[0]), "+f"((d)[1]), "+f"((d)[2]), "+f"((d)[3]) \
        : "r"((a)[0]), "r"((a)[1]), "r"((a)[2]), "r"((a)[3]), "r"(b0), "r"(b1))
#define CP16(dst, src) \
    asm volatile("cp.async.cg.shared.global [%0], [%1], 16;" :: "r"(dst), "l"(src))
#define CP_COMMIT() asm volatile("cp.async.commit_group;" ::: "memory")
#define CP_WAIT0()  asm volatile("cp.async.wait_group 0;" ::: "memory")
#define CP_WAIT1()  asm volatile("cp.async.wait_group 1;" ::: "memory")

__device__ __forceinline__ uint32_t bf2u(bf162 v) {
    uint32_t u; *(bf162*)&u = v; return u;
}
__device__ __forceinline__ void cvt_hilo4(float4 v, bf162& h01, bf162& h23,
                                          bf162& l01, bf162& l23) {
    h01.x = __float2bfloat16(v.x); h01.y = __float2bfloat16(v.y);
    h23.x = __float2bfloat16(v.z); h23.y = __float2bfloat16(v.w);
    l01.x = __float2bfloat16(v.x - __bfloat162float(h01.x));
    l01.y = __float2bfloat16(v.y - __bfloat162float(h01.y));
    l23.x = __float2bfloat16(v.z - __bfloat162float(h23.x));
    l23.y = __float2bfloat16(v.w - __bfloat162float(h23.y));
}
__device__ __forceinline__ uint32_t pack_hilo(float a, float b, uint32_t& lo) {
    bf162 h, l;
    h.x = __float2bfloat16(a); h.y = __float2bfloat16(b);
    l.x = __float2bfloat16(a - __bfloat162float(h.x));
    l.y = __float2bfloat16(b - __bfloat162float(h.y));
    lo = bf2u(l);
    return bf2u(h);
}

// ---------------- x hi/lo conversion ----------------
__global__ void conv_hilo(const float* __restrict__ in, bf16* __restrict__ hi,
                          bf16* __restrict__ lo, int n)
{
    int i = blockIdx.x * blockDim.x + threadIdx.x;
    if (i >= n) return;
    float v = in[i];
    bf16 h = __float2bfloat16(v);
    hi[i] = h;
    lo[i] = __float2bfloat16(v - __bfloat162float(h));
}

// ---------------- RoPE (in place on g_Q and g_Kn) ----------------
__global__ void rope_kernel(const int* __restrict__ spp)
{
    const int nq = MROWS * HH  * (HDIM / 2);
    const int nk = MROWS * KVH * (HDIM / 2);
    int idx = blockIdx.x * blockDim.x + threadIdx.x;
    if (idx >= nq + nk) return;
    const int sp = *spp;

    float* buf; int nh; int i;
    if (idx < nq) { buf = g_Q;  nh = HH;  i = idx; }
    else          { buf = g_Kn; nh = KVH; i = idx - nq; }

    const int j = i & 63;
    const int h = (i >> 6) % nh;
    const int m = i / (64 * nh);
    const int s = m & (SS - 1);

    float p     = (float)(sp + s);
    float theta = powf(10000.0f, -(float)(2 * j) / 128.0f);
    float f     = p * theta;
    float sn, c;
    sincosf(f, &sn, &c);

    float* ptr = buf + ((size_t)m * nh + h) * HDIM + (j << 1);
    float xr = ptr[0], xi = ptr[1];
    ptr[0] = xr * c - xi * sn;
    ptr[1] = xr * sn + xi * c;
}

// ================= HMMA hi/lo GEMM with fused fp32-weight conversion =================
#define G_STAGE 29184
#define G_CONV  (3 * G_STAGE)
#define G_SMEM  (G_CONV + 9216)

__global__ __launch_bounds__(256, 2) void hgemm(
    const bf16* __restrict__ Ah, const bf16* __restrict__ Al,
    const float* __restrict__ W0, float* __restrict__ C0, int N0,
    const float* __restrict__ W1, float* __restrict__ C1, int N1,
    const float* __restrict__ W2, float* __restrict__ C2, int N2)
{
    extern __shared__ char smg[];
    const int t = threadIdx.x, w = t >> 5, lane = t & 31;
    const int wm = w >> 2, wn = w & 3;
    const int bm = blockIdx.y * 128;

    int xt = blockIdx.x;
    const int t0n = N0 >> 6, t1n = N1 >> 6;
    const float* W; float* C; int Nseg, bn;
    if (xt < t0n)            { W = W0; C = C0; Nseg = N0; bn = xt * 64; }
    else if (xt < t0n + t1n) { W = W1; C = C1; Nseg = N1; bn = (xt - t0n) * 64; }
    else                     { W = W2; C = C2; Nseg = N2; bn = (xt - t0n - t1n) * 64; }

    const uint32_t sbase = smem_u32(smg);
    const uint32_t cvh = sbase + G_CONV;

    auto copy_stage = [&](int slot, int ch) {
        const int k0 = ch * 32;
        char* base = smg + slot * G_STAGE;
#pragma unroll
        for (int j = 0; j < 6; j++) {
            int idx = j * 256 + t;
            if (idx < 1024) {
                int hl = idx >> 9, i = idx & 511, r = i >> 2, c = i & 3;
                const bf16* src = (hl ? Al : Ah) + (size_t)(bm + r) * DK + k0 + c * 8;
                CP16(smem_u32(base + hl * 10240 + r * 80 + c * 16), src);
            } else {
                int q = idx - 1024, r = q >> 4, c = q & 15;
                const float* src = W + (size_t)(k0 + r) * Nseg + bn + c * 4;
                CP16(smem_u32(base + 20480 + r * 272 + c * 16), src);
            }
        }
    };

    float acc[4][2][4];
#pragma unroll
    for (int a = 0; a < 4; a++)
#pragma unroll
        for (int bq = 0; bq < 2; bq++)
#pragma unroll
            for (int cix = 0; cix < 4; cix++) acc[a][bq][cix] = 0.f;

    const int NCH = DK / 32;
    copy_stage(0, 0); CP_COMMIT();
    copy_stage(1, 1); CP_COMMIT();

    const uint32_t a_lane = (lane & 15) * 80 + (lane >> 4) * 16;
    const uint32_t bT_lane = (lane & 15) * 144 + (lane >> 4) * 16;

    for (int ch = 0; ch < NCH; ch++) {
        if (ch + 1 < NCH) { CP_WAIT1(); } else { CP_WAIT0(); }
        __syncthreads();

        {
            char* raw = smg + (ch % 3) * G_STAGE + 20480;
#pragma unroll
            for (int j = 0; j < 2; j++) {
                int e = j * 256 + t;
                int r = e >> 4, c4 = e & 15;
                float4 v = *(const float4*)(raw + r * 272 + c4 * 16);
                bf162 h01, h23, l01, l23;
                cvt_hilo4(v, h01, h23, l01, l23);
                char* hp = smg + G_CONV + r * 144 + c4 * 8;
                *(uint2*)(hp)        = make_uint2(bf2u(h01), bf2u(h23));
                *(uint2*)(hp + 4608) = make_uint2(bf2u(l01), bf2u(l23));
            }
        }
        __syncthreads();

        if (ch + 2 < NCH) { copy_stage((ch + 2) % 3, ch + 2); CP_COMMIT(); }

        const uint32_t st = sbase + (ch % 3) * G_STAGE;
        const uint32_t abase = st + (wm * 64) * 80 + a_lane;
#pragma unroll
        for (int ks = 0; ks < 2; ks++) {
            uint32_t ba = cvh + ks * 16 * 144 + bT_lane + wn * 32;
            uint32_t bh_[4], bl_[4];
            LDSM4T(bh_, ba);
            LDSM4T(bl_, ba + 4608);
#pragma unroll
            for (int mt = 0; mt < 4; mt++) {
                uint32_t ah_[4], al_[4];
                uint32_t aa = abase + mt * (16 * 80) + ks * 32;
                LDSM4(ah_, aa);
                LDSM4(al_, aa + 10240);
#pragma unroll
                for (int tn = 0; tn < 2; tn++) {
                    MMA16816(acc[mt][tn], ah_, bh_[tn * 2], bh_[tn * 2 + 1]);
                    MMA16816(acc[mt][tn], ah_, bl_[tn * 2], bl_[tn * 2 + 1]);
                    MMA16816(acc[mt][tn], al_, bh_[tn * 2], bh_[tn * 2 + 1]);
                }
            }
        }
    }

#pragma unroll
    for (int mt = 0; mt < 4; mt++) {
        int r = bm + wm * 64 + mt * 16 + (lane >> 2);
#pragma unroll
        for (int tn = 0; tn < 2; tn++) {
            int c = bn + wn * 16 + tn * 8 + (lane & 3) * 2;
            *(float2*)&C[(size_t)r * Nseg + c]       = make_float2(acc[mt][tn][0], acc[mt][tn][1]);
            *(float2*)&C[(size_t)(r + 8) * Nseg + c] = make_float2(acc[mt][tn][2], acc[mt][tn][3]);
        }
    }
}

// ================= register-resident HMMA flash attention =================
// CTA = (b,kvh,half): 64 q-rows over 2048 keys, chunk 32.
// Warps: 4 m-warps (m16) x 2 k-groups (16 keys each). S/P live in registers;
// softmax via quad-shfl; O per warp m16 x n128; k-groups merged in epilogue.
#define AT_QH  0          // [64][272] bf16 hi, lo at +17408   (34816)
#define AT_KH  34816      // [32][272] hi, lo at +8704         (17408)
#define AT_VH  52224      // same                               (17408)
#define AT_RAW 69632      // rawK [32][528] | rawV +16896       (33792)  reused as rowbuf[64][128]f32
#define AT_ML  103424     // [2 groups][64 rows][2] f32         (1024)
#define ATTN_SMEM 104448
#define NCHA 64           // 2048 / 32

__global__ __launch_bounds__(256, 2) void attn_kernel(const float* __restrict__ cacheK,
                                                      const float* __restrict__ cacheV,
                                                      const int* __restrict__ spp,
                                                      float* __restrict__ pM,
                                                      float* __restrict__ pL,
                                                      float* __restrict__ pC)
{
    extern __shared__ char sm[];
    char* qh = sm + AT_QH;
    char* kh = sm + AT_KH;
    char* vh = sm + AT_VH;
    char* raw = sm + AT_RAW;
    float* mlb = (float*)(sm + AT_ML);

    const int t = threadIdx.x, w = t >> 5, lane = t & 31;
    const int b = blockIdx.x >> 3, kvh = blockIdx.x & 7;
    const int half = blockIdx.y;
    const int pb = half * 128 + blockIdx.x;
    const int kvb = half * 2048;
    const int sp = *spp;
    const int wq = w & 3, gk = w >> 2;          // m-warp, k-group

    const uint32_t u_qh = smem_u32(qh), u_kh = smem_u32(kh), u_vh = smem_u32(vh);

    // cp.async prefetch of raw fp32 K/V chunk (32 keys)
    auto prefetch = [&](int chunk) {
        const int t0 = kvb + chunk * 32;
#pragma unroll
        for (int j = 0; j < 8; j++) {
            int idx = j * 256 + t;
            int tensor = idx >> 10;
            int i = idx & 1023;
            int r = i >> 5, c4 = i & 31;
            int tk = t0 + r;
            const float* src;
            if (tensor == 0)
                src = (tk < sp)
                    ? cacheK + (((size_t)b * MAXS + tk) * KVH + kvh) * HDIM + c4 * 4
                    : g_Kn + (((size_t)b * SS + (tk - sp)) * KVH + kvh) * HDIM + c4 * 4;
            else
                src = (tk < sp)
                    ? cacheV + (((size_t)b * MAXS + tk) * KVH + kvh) * HDIM + c4 * 4
                    : g_Vn + (((size_t)b * SS + (tk - sp)) * KVH + kvh) * HDIM + c4 * 4;
            CP16(smem_u32(raw + tensor * 16896 + r * 528 + c4 * 16), src);
        }
    };

    prefetch(0); CP_COMMIT();

    // Q load + hi/lo convert into smem (packed 8B stores)
#pragma unroll
    for (int j = 0; j < 8; j++) {
        int idx = j * 256 + t;
        int r = idx >> 5, c4 = idx & 31;
        const float4 v = *(const float4*)(g_Q +
            (((size_t)b * SS + (r & 15)) * HH + kvh * 4 + (r >> 4)) * HDIM + c4 * 4);
        bf162 h01, h23, l01, l23;
        cvt_hilo4(v, h01, h23, l01, l23);
        char* hp = qh + r * 272 + c4 * 8;
        *(uint2*)(hp)         = make_uint2(bf2u(h01), bf2u(h23));
        *(uint2*)(hp + 17408) = make_uint2(bf2u(l01), bf2u(l23));
    }

    // per-thread softmax state: rows r0 = wq*16 + lane/4, r1 = r0+8
    const int r0 = wq * 16 + (lane >> 2);
    const int r1 = r0 + 8;
    float mA = __int_as_float(0xff800000), mB = mA;   // row maxes
    float lA = 0.f, lB = 0.f;                          // row sums

    float oacc[16][4];
#pragma unroll
    for (int nt = 0; nt < 16; nt++)
#pragma unroll
        for (int cix = 0; cix < 4; cix++) oacc[nt][cix] = 0.f;

    const float scale = 0.08838834764831845f;   // 1/sqrt(128)
    const uint32_t a_lane = (lane & 15) * 272 + (lane >> 4) * 16;
    const uint32_t b_row  = (lane & 7) + ((lane >> 4) << 3);
    const uint32_t b_col  = ((lane >> 3) & 1) * 16;

    for (int ch = 0; ch < NCHA; ch++) {
        CP_WAIT0();
        __syncthreads();            // raw ready; all warps done with prior kh/vh

        // convert raw fp32 -> bf16 hi/lo K/V tiles
#pragma unroll
        for (int j = 0; j < 8; j++) {
            int idx = j * 256 + t;
            int tensor = idx >> 10;
            int i = idx & 1023;
            int r = i >> 5, c4 = i & 31;
            float4 v = *(const float4*)(raw + tensor * 16896 + r * 528 + c4 * 16);
            bf162 h01, h23, l01, l23;
            cvt_hilo4(v, h01, h23, l01, l23);
            char* hp = (tensor ? vh : kh) + r * 272 + c4 * 8;
            *(uint2*)(hp)        = make_uint2(bf2u(h01), bf2u(h23));
            *(uint2*)(hp + 8704) = make_uint2(bf2u(l01), bf2u(l23));
        }
        __syncthreads();            // tiles visible; raw free

        if (ch + 1 < NCHA) { prefetch(ch + 1); CP_COMMIT(); }

        // ---- S = Q K^T (3-pass hi/lo): warp tile m16 x n16 (its k-group's keys) ----
        float sacc[2][4];
#pragma unroll
        for (int tn = 0; tn < 2; tn++)
#pragma unroll
            for (int cix = 0; cix < 4; cix++) sacc[tn][cix] = 0.f;

        const uint32_t kb = u_kh + (gk * 16 + b_row) * 272 + b_col;
#pragma unroll
        for (int ks = 0; ks < 8; ks++) {
            const int ko = ks * 32;
            uint32_t bh_[4], bl_[4];
            LDSM4(bh_, kb + ko);
            LDSM4(bl_, kb + ko + 8704);
            uint32_t aa = u_qh + (wq * 16) * 272 + a_lane + ko;
            uint32_t ah_[4], al_[4];
            LDSM4(ah_, aa);
            LDSM4(al_, aa + 17408);
#pragma unroll
            for (int tn = 0; tn < 2; tn++) {
                MMA16816(sacc[tn], ah_, bh_[tn * 2], bh_[tn * 2 + 1]);
                MMA16816(sacc[tn], ah_, bl_[tn * 2], bl_[tn * 2 + 1]);
                MMA16816(sacc[tn], al_, bh_[tn * 2], bh_[tn * 2 + 1]);
            }
        }

        // ---- in-register online softmax (rows r0, r1; 16 cols in quad) ----
        float s00 = sacc[0][0] * scale, s01 = sacc[0][1] * scale;
        float s02 = sacc[1][0] * scale, s03 = sacc[1][1] * scale;   // row r0
        float s10 = sacc[0][2] * scale, s11 = sacc[0][3] * scale;
        float s12 = sacc[1][2] * scale, s13 = sacc[1][3] * scale;   // row r1

        float mx0 = fmaxf(fmaxf(s00, s01), fmaxf(s02, s03));
        float mx1 = fmaxf(fmaxf(s10, s11), fmaxf(s12, s13));
#pragma unroll
        for (int o = 1; o <= 2; o <<= 1) {
            mx0 = fmaxf(mx0, __shfl_xor_sync(0xffffffffu, mx0, o));
            mx1 = fmaxf(mx1, __shfl_xor_sync(0xffffffffu, mx1, o));
        }
        float m0n = fmaxf(mA, mx0), m1n = fmaxf(mB, mx1);
        float c0 = __expf(mA - m0n), c1 = __expf(mB - m1n);

        float e00 = __expf(s00 - m0n), e01 = __expf(s01 - m0n);
        float e02 = __expf(s02 - m0n), e03 = __expf(s03 - m0n);
        float e10 = __expf(s10 - m1n), e11 = __expf(s11 - m1n);
        float e12 = __expf(s12 - m1n), e13 = __expf(s13 - m1n);

        float sum0 = e00 + e01 + e02 + e03;
        float sum1 = e10 + e11 + e12 + e13;
#pragma unroll
        for (int o = 1; o <= 2; o <<= 1) {
            sum0 += __shfl_xor_sync(0xffffffffu, sum0, o);
            sum1 += __shfl_xor_sync(0xffffffffu, sum1, o);
        }
        lA = lA * c0 + sum0;  mA = m0n;
        lB = lB * c1 + sum1;  mB = m1n;

        // P fragments (m16k16 A layout) hi/lo from the exp'd values
        uint32_t ph_[4], pl_[4];
        ph_[0] = pack_hilo(e00, e01, pl_[0]);
        ph_[1] = pack_hilo(e10, e11, pl_[1]);
        ph_[2] = pack_hilo(e02, e03, pl_[2]);
        ph_[3] = pack_hilo(e12, e13, pl_[3]);

        // rescale O accumulators
#pragma unroll
        for (int nt = 0; nt < 16; nt++) {
            oacc[nt][0] *= c0; oacc[nt][1] *= c0;
            oacc[nt][2] *= c1; oacc[nt][3] *= c1;
        }

        // ---- O += P V (3-pass hi/lo): k16 (group keys), n128 ----
        const uint32_t vb = u_vh + (gk * 16 + (lane & 15)) * 272 + (lane >> 4) * 16;
#pragma unroll
        for (int nc = 0; nc < 8; nc++) {
            uint32_t va = vb + nc * 32;
            uint32_t vbh[4], vbl[4];
            LDSM4T(vbh, va);
            LDSM4T(vbl, va + 8704);
#pragma unroll
            for (int sub = 0; sub < 2; sub++) {
                int nt = nc * 2 + sub;
                MMA16816(oacc[nt], ph_, vbh[sub * 2], vbh[sub * 2 + 1]);
                MMA16816(oacc[nt], ph_, vbl[sub * 2], vbl[sub * 2 + 1]);
                MMA16816(oacc[nt], pl_, vbh[sub * 2], vbh[sub * 2 + 1]);
            }
        }
    }

    // ================= epilogue: merge the two k-groups, write partials =================
    __syncthreads();                         // raw buffer free for reuse
    float* rowbuf = (float*)raw;             // [64][128]
    if ((lane & 3) == 0) {
        mlb[(gk * 64 + r0) * 2 + 0] = mA;  mlb[(gk * 64 + r0) * 2 + 1] = lA;
        mlb[(gk * 64 + r1) * 2 + 0] = mB;  mlb[(gk * 64 + r1) * 2 + 1] = lB;
    }
    if (gk == 1) {
#pragma unroll
        for (int nt = 0; nt < 16; nt++) {
            int c = nt * 8 + (lane & 3) * 2;
            *(float2*)&rowbuf[r0 * 128 + c] = make_float2(oacc[nt][0], oacc[nt][1]);
            *(float2*)&rowbuf[r1 * 128 + c] = make_float2(oacc[nt][2], oacc[nt][3]);
        }
    }
    __syncthreads();
    if (gk == 0) {
        float m1r0 = mlb[(64 + r0) * 2 + 0], l1r0 = mlb[(64 + r0) * 2 + 1];
        float m1r1 = mlb[(64 + r1) * 2 + 0], l1r1 = mlb[(64 + r1) * 2 + 1];
        float M0 = fmaxf(mA, m1r0), M1 = fmaxf(mB, m1r1);
        float w00 = __expf(mA - M0), w01 = __expf(m1r0 - M0);
        float w10 = __expf(mB - M1), w11 = __expf(m1r1 - M1);
        float L0 = lA * w00 + l1r0 * w01;
        float L1 = lB * w10 + l1r1 * w11;
#pragma unroll
        for (int nt = 0; nt < 16; nt++) {
            int c = nt * 8 + (lane & 3) * 2;
            float2 o1a = *(float2*)&rowbuf[r0 * 128 + c];
            float2 o1b = *(float2*)&rowbuf[r1 * 128 + c];
            *(float2*)&pC[((size_t)pb * 64 + r0) * 128 + c] =
                make_float2(oacc[nt][0] * w00 + o1a.x * w01,
                            oacc[nt][1] * w00 + o1a.y * w01);
            *(float2*)&pC[((size_t)pb * 64 + r1) * 128 + c] =
                make_float2(oacc[nt][2] * w10 + o1b.x * w11,
                            oacc[nt][3] * w10 + o1b.y * w11);
        }
        if ((lane & 3) == 0) {
            pM[pb * 64 + r0] = M0;  pL[pb * 64 + r0] = L0;
            pM[pb * 64 + r1] = M1;  pL[pb * 64 + r1] = L1;
        }
    }
}

// ---------------- combine halves + convert ctx to bf16 hi/lo ----------------
__global__ void combine_kernel(const float* __restrict__ pM, const float* __restrict__ pL,
                               const float* __restrict__ pC,
                               bf16* __restrict__ Chi, bf16* __restrict__ Clo)
{
    const int bq  = blockIdx.x;          // 0..127
    const int b   = bq >> 3;
    const int kvh = bq & 7;
    const int t   = threadIdx.x;

    for (int idx = t; idx < 64 * 128; idx += 256) {
        int r = idx >> 7;
        int d = idx & 127;
        float m0 = pM[bq * 64 + r],         m1 = pM[(128 + bq) * 64 + r];
        float l0 = pL[bq * 64 + r],         l1 = pL[(128 + bq) * 64 + r];
        float m  = fmaxf(m0, m1);
        float w0 = __expf(m0 - m), w1 = __expf(m1 - m);
        float l  = l0 * w0 + l1 * w1;
        float c0 = pC[((size_t)bq * 64 + r) * 128 + d];
        float c1 = pC[((size_t)(128 + bq) * 64 + r) * 128 + d];
        float v  = (c0 * w0 + c1 * w1) / l;

        int rep = r >> 4, s = r & 15;
        size_t o = ((size_t)(b * SS + s) * HH + kvh * 4 + rep) * HDIM + d;
        bf16 hi = __float2bfloat16(v);
        Chi[o] = hi;
        Clo[o] = __float2bfloat16(v - __bfloat162float(hi));
    }
}

// ---------------- launch ----------------
extern "C" void kernel_launch(void* const* d_in, const int* in_sizes, int n_in,
                              void* d_out, int out_size)
{
    const float* x      = (const float*)d_in[0];
    const float* Wq     = (const float*)d_in[1];
    const float* Wk     = (const float*)d_in[2];
    const float* Wv     = (const float*)d_in[3];
    const float* Wo     = (const float*)d_in[4];
    const float* cacheK = (const float*)d_in[5];
    const float* cacheV = (const float*)d_in[6];
    const int*   spp    = (const int*)  d_in[7];
    float*       out    = (float*)d_out;
    (void)in_sizes; (void)n_in; (void)out_size;

    void *xh, *xl, *ch, *cl, *qp, *kp, *vp, *pm, *pl, *pc;
    cudaGetSymbolAddress(&xh, g_Xhi);  cudaGetSymbolAddress(&xl, g_Xlo);
    cudaGetSymbolAddress(&ch, g_Chi);  cudaGetSymbolAddress(&cl, g_Clo);
    cudaGetSymbolAddress(&qp, g_Q);    cudaGetSymbolAddress(&kp, g_Kn);
    cudaGetSymbolAddress(&vp, g_Vn);
    cudaGetSymbolAddress(&pm, g_pM);   cudaGetSymbolAddress(&pl, g_pL);
    cudaGetSymbolAddress(&pc, g_pC);

    cudaFuncSetAttribute(hgemm, cudaFuncAttributeMaxDynamicSharedMemorySize, G_SMEM);
    cudaFuncSetAttribute(attn_kernel, cudaFuncAttributeMaxDynamicSharedMemorySize, ATTN_SMEM);

    dim3 blk(256);
    conv_hilo<<<4096, 256>>>(x, (bf16*)xh, (bf16*)xl, MROWS * DK);

    hgemm<<<dim3(96, 2), blk, G_SMEM>>>(
        (bf16*)xh, (bf16*)xl,
        Wq, (float*)qp, 4096,
        Wk, (float*)kp, 1024,
        Wv, (float*)vp, 1024);

    {
        int total = MROWS * HH * 64 + MROWS * KVH * 64;
        rope_kernel<<<(total + 255) / 256, 256>>>(spp);
    }

    attn_kernel<<<dim3(128, 2), blk, ATTN_SMEM>>>(cacheK, cacheV, spp,
                                                  (float*)pm, (float*)pl, (float*)pc);
    combine_kernel<<<128, blk>>>((float*)pm, (float*)pl, (float*)pc,
                                 (bf16*)ch, (bf16*)cl);

    hgemm<<<dim3(64, 2), blk, G_SMEM>>>(
        (bf16*)ch, (bf16*)cl,
        Wo, out, 4096,
        (const float*)0, (float*)0, 0,
        (const float*)0, (float*)0, 0);
}

// round 10
// speedup vs baseline: 4.2575x; 1.1661x over previous
#include <cuda_runtime.h>
#include <cuda_bf16.h>
#include <math.h>
#include <stdint.h>

// ---------------- problem constants ----------------
#define BB    16
#define SS    16
#define HH    32
#define KVH   8
#define HDIM  128
#define MAXS  4096
#define MROWS 256
#define DK    4096
#define KVLEN 4096

typedef __nv_bfloat16  bf16;
typedef __nv_bfloat162 bf162;

// ---------------- device scratch ----------------
__device__ float g_Xt[MROWS * DK];      // x, tf32-rounded
__device__ float g_Ct[MROWS * DK];      // ctx, tf32-rounded
__device__ float g_Q [MROWS * 4096];
__device__ float g_Kn[MROWS * 1024];
__device__ float g_Vn[MROWS * 1024];
__device__ float g_pM[2 * 128 * 64], g_pL[2 * 128 * 64];
__device__ float g_pC[2 * 128 * 64 * 128];

// ---------------- PTX helpers (baseline ISA only — no tcgen05 on compute_103) ----------------
__device__ __forceinline__ uint32_t smem_u32(const void* p) {
    uint32_t a;
    asm("{ .reg .u64 t; cvta.to.shared.u64 t, %1; cvt.u32.u64 %0, t; }" : "=r"(a) : "l"(p));
    return a;
}
#define LDSM4(r, addr) \
    asm volatile("ldmatrix.sync.aligned.m8n8.x4.shared.b16 {%0,%1,%2,%3}, [%4];" \
        : "=r"((r)[0]), "=r"((r)[1]), "=r"((r)[2]), "=r"((r)[3]) : "r"(addr))
#define LDSM4T(r, addr) \
    asm volatile("ldmatrix.sync.aligned.m8n8.x4.trans.shared.b16 {%0,%1,%2,%3}, [%4];" \
        : "=r"((r)[0]), "=r"((r)[1]), "=r"((r)[2]), "=r"((r)[3]) : "r"(addr))
#define MMA16816(d, a, b0, b1) \
    asm volatile("mma.sync.aligned.m16n8k16.row.col.f32.bf16.bf16.f32 " \
        "{%0,%1,%2,%3}, {%4,%5,%6,%7}, {%8,%9}, {%0,%1,%2,%3};" \
        : "+f"((d)[0]), "+f"((d)[1]), "+f"((d)[2]), "+f"((d)[3]) \
        : "r"((a)[0]), "r"((a)[1]), "r"((a)[2]), "r"((a)[3]), "r"(b0), "r"(b1))
#define MMATF32(d, a, b0, b1) \
    asm volatile("mma.sync.aligned.m16n8k8.row.col.f32.tf32.tf32.f32 " \
        "{%0,%1,%2,%3}, {%4,%5,%6,%7}, {%8,%9}, {%0,%1,%2,%3};" \
        : "+f"((d)[0]), "+f"((d)[1]), "+f"((d)[2]), "+f"((d)[3]) \
        : "r"((a)[0]), "r"((a)[1]), "r"((a)[2]), "r"((a)[3]), "r"(b0), "r"(b1))
#define CP16(dst, src) \
    asm volatile("cp.async.cg.shared.global [%0], [%1], 16;" :: "r"(dst), "l"(src))
#define CP_COMMIT() asm volatile("cp.async.commit_group;" ::: "memory")
#define CP_WAIT0()  asm volatile("cp.async.wait_group 0;" ::: "memory")
#define CP_WAIT1()  asm volatile("cp.async.wait_group 1;" ::: "memory")

__device__ __forceinline__ uint32_t f2tf(float f) {
    uint32_t r;
    asm("cvt.rna.tf32.f32 %0, %1;" : "=r"(r) : "f"(f));
    return r;
}
__device__ __forceinline__ uint32_t bf2u(bf162 v) {
    uint32_t u; *(bf162*)&u = v; return u;
}
__device__ __forceinline__ void cvt_hilo4(float4 v, bf162& h01, bf162& h23,
                                          bf162& l01, bf162& l23) {
    h01.x = __float2bfloat16(v.x); h01.y = __float2bfloat16(v.y);
    h23.x = __float2bfloat16(v.z); h23.y = __float2bfloat16(v.w);
    l01.x = __float2bfloat16(v.x - __bfloat162float(h01.x));
    l01.y = __float2bfloat16(v.y - __bfloat162float(h01.y));
    l23.x = __float2bfloat16(v.z - __bfloat162float(h23.x));
    l23.y = __float2bfloat16(v.w - __bfloat162float(h23.y));
}
__device__ __forceinline__ uint32_t pack_hilo(float a, float b, uint32_t& lo) {
    bf162 h, l;
    h.x = __float2bfloat16(a); h.y = __float2bfloat16(b);
    l.x = __float2bfloat16(a - __bfloat162float(h.x));
    l.y = __float2bfloat16(b - __bfloat162float(h.y));
    lo = bf2u(l);
    return bf2u(h);
}

// ---------------- x tf32 pre-rounding ----------------
__global__ void conv_tf32(const float* __restrict__ in, float* __restrict__ outp, int n)
{
    int i = blockIdx.x * blockDim.x + threadIdx.x;
    if (i >= n) return;
    outp[i] = __uint_as_float(f2tf(in[i]));
}

// ---------------- RoPE (in place on g_Q and g_Kn) ----------------
__global__ void rope_kernel(const int* __restrict__ spp)
{
    const int nq = MROWS * HH  * (HDIM / 2);
    const int nk = MROWS * KVH * (HDIM / 2);
    int idx = blockIdx.x * blockDim.x + threadIdx.x;
    if (idx >= nq + nk) return;
    const int sp = *spp;

    float* buf; int nh; int i;
    if (idx < nq) { buf = g_Q;  nh = HH;  i = idx; }
    else          { buf = g_Kn; nh = KVH; i = idx - nq; }

    const int j = i & 63;
    const int h = (i >> 6) % nh;
    const int m = i / (64 * nh);
    const int s = m & (SS - 1);

    float p     = (float)(sp + s);
    float theta = powf(10000.0f, -(float)(2 * j) / 128.0f);
    float f     = p * theta;
    float sn, c;
    sincosf(f, &sn, &c);

    float* ptr = buf + ((size_t)m * nh + h) * HDIM + (j << 1);
    float xr = ptr[0], xi = ptr[1];
    ptr[0] = xr * c - xi * sn;
    ptr[1] = xr * sn + xi * c;
}

// ================= tf32 single-pass GEMM: C = A[256,4096] @ W[4096,N] =================
// Tile 128x64, chunk K=32, 3-stage cp.async pipeline, fp32 operands fed as tf32.
// Stage: A[128 rows][144B] (18432) + W[32 rows][288B] (9216) = 27648.
#define T_STAGE 27648
#define T_SMEM  (3 * T_STAGE)

__global__ __launch_bounds__(256, 2) void tgemm(
    const float* __restrict__ A,
    const float* __restrict__ W0, float* __restrict__ C0, int N0,
    const float* __restrict__ W1, float* __restrict__ C1, int N1,
    const float* __restrict__ W2, float* __restrict__ C2, int N2)
{
    extern __shared__ char smg[];
    const int t = threadIdx.x, w = t >> 5, lane = t & 31;
    const int wm = w >> 2, wn = w & 3;          // 2 m-warps x 4 n-warps
    const int bm = blockIdx.y * 128;

    int xt = blockIdx.x;
    const int t0n = N0 >> 6, t1n = N1 >> 6;
    const float* W; float* C; int Nseg, bn;
    if (xt < t0n)            { W = W0; C = C0; Nseg = N0; bn = xt * 64; }
    else if (xt < t0n + t1n) { W = W1; C = C1; Nseg = N1; bn = (xt - t0n) * 64; }
    else                     { W = W2; C = C2; Nseg = N2; bn = (xt - t0n - t1n) * 64; }

    // stage copier: A 1024 cp16 + W 512 cp16 = 6 per thread
    auto copy_stage = [&](int slot, int ch) {
        const int k0 = ch * 32;
        char* base = smg + slot * T_STAGE;
#pragma unroll
        for (int j = 0; j < 6; j++) {
            int idx = j * 256 + t;
            if (idx < 1024) {
                int r = idx >> 3, c = idx & 7;                // row, 16B col
                const float* src = A + (size_t)(bm + r) * DK + k0 + c * 4;
                CP16(smem_u32(base + r * 144 + c * 16), src);
            } else {
                int q = idx - 1024, r = q >> 4, c = q & 15;   // 32 k-rows x 16 cols
                const float* src = W + (size_t)(k0 + r) * Nseg + bn + c * 4;
                CP16(smem_u32(base + 18432 + r * 288 + c * 16), src);
            }
        }
    };

    float acc[4][2][4];
#pragma unroll
    for (int a = 0; a < 4; a++)
#pragma unroll
        for (int bq = 0; bq < 2; bq++)
#pragma unroll
            for (int cix = 0; cix < 4; cix++) acc[a][bq][cix] = 0.f;

    const int NCH = DK / 32;       // 128
    copy_stage(0, 0); CP_COMMIT();
    copy_stage(1, 1); CP_COMMIT();

    const int lq = lane >> 2, lr = lane & 3;

    for (int ch = 0; ch < NCH; ch++) {
        if (ch + 1 < NCH) { CP_WAIT1(); } else { CP_WAIT0(); }
        __syncthreads();     // stage ready; all warps done with chunk ch-1

        if (ch + 2 < NCH) { copy_stage((ch + 2) % 3, ch + 2); CP_COMMIT(); }

        const float* stA = (const float*)(smg + (ch % 3) * T_STAGE);          // stride 36 f
        const float* stW = (const float*)(smg + (ch % 3) * T_STAGE + 18432);  // stride 72 f

#pragma unroll
        for (int ks = 0; ks < 4; ks++) {
            // B fragments: rows ks*8 + lr, + 4; col wn*16 + tn*8 + lq
            uint32_t bf[2][2];
#pragma unroll
            for (int tn = 0; tn < 2; tn++) {
                int col = wn * 16 + tn * 8 + lq;
                int kr = ks * 8 + lr;
                bf[tn][0] = f2tf(stW[kr * 72 + col]);
                bf[tn][1] = f2tf(stW[(kr + 4) * 72 + col]);
            }
#pragma unroll
            for (int mt = 0; mt < 4; mt++) {
                int ar = wm * 64 + mt * 16 + lq;
                int ac = ks * 8 + lr;
                uint32_t af[4];
                af[0] = __float_as_uint(stA[ar * 36 + ac]);
                af[1] = __float_as_uint(stA[(ar + 8) * 36 + ac]);
                af[2] = __float_as_uint(stA[ar * 36 + ac + 4]);
                af[3] = __float_as_uint(stA[(ar + 8) * 36 + ac + 4]);
#pragma unroll
                for (int tn = 0; tn < 2; tn++)
                    MMATF32(acc[mt][tn], af, bf[tn][0], bf[tn][1]);
            }
        }
    }

    // epilogue
#pragma unroll
    for (int mt = 0; mt < 4; mt++) {
        int r = bm + wm * 64 + mt * 16 + lq;
#pragma unroll
        for (int tn = 0; tn < 2; tn++) {
            int c = bn + wn * 16 + tn * 8 + lr * 2;
            *(float2*)&C[(size_t)r * Nseg + c]       = make_float2(acc[mt][tn][0], acc[mt][tn][1]);
            *(float2*)&C[(size_t)(r + 8) * Nseg + c] = make_float2(acc[mt][tn][2], acc[mt][tn][3]);
        }
    }
}

// ================= register-resident HMMA flash attention (unchanged from R8) =================
#define AT_QH  0
#define AT_KH  34816
#define AT_VH  52224
#define AT_RAW 69632
#define AT_ML  103424
#define ATTN_SMEM 104448
#define NCHA 64

__global__ __launch_bounds__(256, 2) void attn_kernel(const float* __restrict__ cacheK,
                                                      const float* __restrict__ cacheV,
                                                      const int* __restrict__ spp,
                                                      float* __restrict__ pM,
                                                      float* __restrict__ pL,
                                                      float* __restrict__ pC)
{
    extern __shared__ char sm[];
    char* qh = sm + AT_QH;
    char* kh = sm + AT_KH;
    char* vh = sm + AT_VH;
    char* raw = sm + AT_RAW;
    float* mlb = (float*)(sm + AT_ML);

    const int t = threadIdx.x, w = t >> 5, lane = t & 31;
    const int b = blockIdx.x >> 3, kvh = blockIdx.x & 7;
    const int half = blockIdx.y;
    const int pb = half * 128 + blockIdx.x;
    const int kvb = half * 2048;
    const int sp = *spp;
    const int wq = w & 3, gk = w >> 2;

    const uint32_t u_qh = smem_u32(qh), u_kh = smem_u32(kh), u_vh = smem_u32(vh);

    auto prefetch = [&](int chunk) {
        const int t0 = kvb + chunk * 32;
#pragma unroll
        for (int j = 0; j < 8; j++) {
            int idx = j * 256 + t;
            int tensor = idx >> 10;
            int i = idx & 1023;
            int r = i >> 5, c4 = i & 31;
            int tk = t0 + r;
            const float* src;
            if (tensor == 0)
                src = (tk < sp)
                    ? cacheK + (((size_t)b * MAXS + tk) * KVH + kvh) * HDIM + c4 * 4
                    : g_Kn + (((size_t)b * SS + (tk - sp)) * KVH + kvh) * HDIM + c4 * 4;
            else
                src = (tk < sp)
                    ? cacheV + (((size_t)b * MAXS + tk) * KVH + kvh) * HDIM + c4 * 4
                    : g_Vn + (((size_t)b * SS + (tk - sp)) * KVH + kvh) * HDIM + c4 * 4;
            CP16(smem_u32(raw + tensor * 16896 + r * 528 + c4 * 16), src);
        }
    };

    prefetch(0); CP_COMMIT();

#pragma unroll
    for (int j = 0; j < 8; j++) {
        int idx = j * 256 + t;
        int r = idx >> 5, c4 = idx & 31;
        const float4 v = *(const float4*)(g_Q +
            (((size_t)b * SS + (r & 15)) * HH + kvh * 4 + (r >> 4)) * HDIM + c4 * 4);
        bf162 h01, h23, l01, l23;
        cvt_hilo4(v, h01, h23, l01, l23);
        char* hp = qh + r * 272 + c4 * 8;
        *(uint2*)(hp)         = make_uint2(bf2u(h01), bf2u(h23));
        *(uint2*)(hp + 17408) = make_uint2(bf2u(l01), bf2u(l23));
    }

    const int r0 = wq * 16 + (lane >> 2);
    const int r1 = r0 + 8;
    float mA = __int_as_float(0xff800000), mB = mA;
    float lA = 0.f, lB = 0.f;

    float oacc[16][4];
#pragma unroll
    for (int nt = 0; nt < 16; nt++)
#pragma unroll
        for (int cix = 0; cix < 4; cix++) oacc[nt][cix] = 0.f;

    const float scale = 0.08838834764831845f;
    const uint32_t a_lane = (lane & 15) * 272 + (lane >> 4) * 16;
    const uint32_t b_row  = (lane & 7) + ((lane >> 4) << 3);
    const uint32_t b_col  = ((lane >> 3) & 1) * 16;

    for (int ch = 0; ch < NCHA; ch++) {
        CP_WAIT0();
        __syncthreads();

#pragma unroll
        for (int j = 0; j < 8; j++) {
            int idx = j * 256 + t;
            int tensor = idx >> 10;
            int i = idx & 1023;
            int r = i >> 5, c4 = i & 31;
            float4 v = *(const float4*)(raw + tensor * 16896 + r * 528 + c4 * 16);
            bf162 h01, h23, l01, l23;
            cvt_hilo4(v, h01, h23, l01, l23);
            char* hp = (tensor ? vh : kh) + r * 272 + c4 * 8;
            *(uint2*)(hp)        = make_uint2(bf2u(h01), bf2u(h23));
            *(uint2*)(hp + 8704) = make_uint2(bf2u(l01), bf2u(l23));
        }
        __syncthreads();

        if (ch + 1 < NCHA) { prefetch(ch + 1); CP_COMMIT(); }

        float sacc[2][4];
#pragma unroll
        for (int tn = 0; tn < 2; tn++)
#pragma unroll
            for (int cix = 0; cix < 4; cix++) sacc[tn][cix] = 0.f;

        const uint32_t kb = u_kh + (gk * 16 + b_row) * 272 + b_col;
#pragma unroll
        for (int ks = 0; ks < 8; ks++) {
            const int ko = ks * 32;
            uint32_t bh_[4], bl_[4];
            LDSM4(bh_, kb + ko);
            LDSM4(bl_, kb + ko + 8704);
            uint32_t aa = u_qh + (wq * 16) * 272 + a_lane + ko;
            uint32_t ah_[4], al_[4];
            LDSM4(ah_, aa);
            LDSM4(al_, aa + 17408);
#pragma unroll
            for (int tn = 0; tn < 2; tn++) {
                MMA16816(sacc[tn], ah_, bh_[tn * 2], bh_[tn * 2 + 1]);
                MMA16816(sacc[tn], ah_, bl_[tn * 2], bl_[tn * 2 + 1]);
                MMA16816(sacc[tn], al_, bh_[tn * 2], bh_[tn * 2 + 1]);
            }
        }

        float s00 = sacc[0][0] * scale, s01 = sacc[0][1] * scale;
        float s02 = sacc[1][0] * scale, s03 = sacc[1][1] * scale;
        float s10 = sacc[0][2] * scale, s11 = sacc[0][3] * scale;
        float s12 = sacc[1][2] * scale, s13 = sacc[1][3] * scale;

        float mx0 = fmaxf(fmaxf(s00, s01), fmaxf(s02, s03));
        float mx1 = fmaxf(fmaxf(s10, s11), fmaxf(s12, s13));
#pragma unroll
        for (int o = 1; o <= 2; o <<= 1) {
            mx0 = fmaxf(mx0, __shfl_xor_sync(0xffffffffu, mx0, o));
            mx1 = fmaxf(mx1, __shfl_xor_sync(0xffffffffu, mx1, o));
        }
        float m0n = fmaxf(mA, mx0), m1n = fmaxf(mB, mx1);
        float c0 = __expf(mA - m0n), c1 = __expf(mB - m1n);

        float e00 = __expf(s00 - m0n), e01 = __expf(s01 - m0n);
        float e02 = __expf(s02 - m0n), e03 = __expf(s03 - m0n);
        float e10 = __expf(s10 - m1n), e11 = __expf(s11 - m1n);
        float e12 = __expf(s12 - m1n), e13 = __expf(s13 - m1n);

        float sum0 = e00 + e01 + e02 + e03;
        float sum1 = e10 + e11 + e12 + e13;
#pragma unroll
        for (int o = 1; o <= 2; o <<= 1) {
            sum0 += __shfl_xor_sync(0xffffffffu, sum0, o);
            sum1 += __shfl_xor_sync(0xffffffffu, sum1, o);
        }
        lA = lA * c0 + sum0;  mA = m0n;
        lB = lB * c1 + sum1;  mB = m1n;

        uint32_t ph_[4], pl_[4];
        ph_[0] = pack_hilo(e00, e01, pl_[0]);
        ph_[1] = pack_hilo(e10, e11, pl_[1]);
        ph_[2] = pack_hilo(e02, e03, pl_[2]);
        ph_[3] = pack_hilo(e12, e13, pl_[3]);

#pragma unroll
        for (int nt = 0; nt < 16; nt++) {
            oacc[nt][0] *= c0; oacc[nt][1] *= c0;
            oacc[nt][2] *= c1; oacc[nt][3] *= c1;
        }

        const uint32_t vb = u_vh + (gk * 16 + (lane & 15)) * 272 + (lane >> 4) * 16;
#pragma unroll
        for (int nc = 0; nc < 8; nc++) {
            uint32_t va = vb + nc * 32;
            uint32_t vbh[4], vbl[4];
            LDSM4T(vbh, va);
            LDSM4T(vbl, va + 8704);
#pragma unroll
            for (int sub = 0; sub < 2; sub++) {
                int nt = nc * 2 + sub;
                MMA16816(oacc[nt], ph_, vbh[sub * 2], vbh[sub * 2 + 1]);
                MMA16816(oacc[nt], ph_, vbl[sub * 2], vbl[sub * 2 + 1]);
                MMA16816(oacc[nt], pl_, vbh[sub * 2], vbh[sub * 2 + 1]);
            }
        }
    }

    __syncthreads();
    float* rowbuf = (float*)raw;
    if ((lane & 3) == 0) {
        mlb[(gk * 64 + r0) * 2 + 0] = mA;  mlb[(gk * 64 + r0) * 2 + 1] = lA;
        mlb[(gk * 64 + r1) * 2 + 0] = mB;  mlb[(gk * 64 + r1) * 2 + 1] = lB;
    }
    if (gk == 1) {
#pragma unroll
        for (int nt = 0; nt < 16; nt++) {
            int c = nt * 8 + (lane & 3) * 2;
            *(float2*)&rowbuf[r0 * 128 + c] = make_float2(oacc[nt][0], oacc[nt][1]);
            *(float2*)&rowbuf[r1 * 128 + c] = make_float2(oacc[nt][2], oacc[nt][3]);
        }
    }
    __syncthreads();
    if (gk == 0) {
        float m1r0 = mlb[(64 + r0) * 2 + 0], l1r0 = mlb[(64 + r0) * 2 + 1];
        float m1r1 = mlb[(64 + r1) * 2 + 0], l1r1 = mlb[(64 + r1) * 2 + 1];
        float M0 = fmaxf(mA, m1r0), M1 = fmaxf(mB, m1r1);
        float w00 = __expf(mA - M0), w01 = __expf(m1r0 - M0);
        float w10 = __expf(mB - M1), w11 = __expf(m1r1 - M1);
        float L0 = lA * w00 + l1r0 * w01;
        float L1 = lB * w10 + l1r1 * w11;
#pragma unroll
        for (int nt = 0; nt < 16; nt++) {
            int c = nt * 8 + (lane & 3) * 2;
            float2 o1a = *(float2*)&rowbuf[r0 * 128 + c];
            float2 o1b = *(float2*)&rowbuf[r1 * 128 + c];
            *(float2*)&pC[((size_t)pb * 64 + r0) * 128 + c] =
                make_float2(oacc[nt][0] * w00 + o1a.x * w01,
                            oacc[nt][1] * w00 + o1a.y * w01);
            *(float2*)&pC[((size_t)pb * 64 + r1) * 128 + c] =
                make_float2(oacc[nt][2] * w10 + o1b.x * w11,
                            oacc[nt][3] * w10 + o1b.y * w11);
        }
        if ((lane & 3) == 0) {
            pM[pb * 64 + r0] = M0;  pL[pb * 64 + r0] = L0;
            pM[pb * 64 + r1] = M1;  pL[pb * 64 + r1] = L1;
        }
    }
}

// ---------------- combine halves -> tf32-rounded fp32 ctx ----------------
__global__ void combine_kernel(const float* __restrict__ pM, const float* __restrict__ pL,
                               const float* __restrict__ pC, float* __restrict__ Ct)
{
    const int bq  = blockIdx.x;          // 0..127
    const int b   = bq >> 3;
    const int kvh = bq & 7;
    const int t   = threadIdx.x;

    for (int idx = t; idx < 64 * 128; idx += 256) {
        int r = idx >> 7;
        int d = idx & 127;
        float m0 = pM[bq * 64 + r],         m1 = pM[(128 + bq) * 64 + r];
        float l0 = pL[bq * 64 + r],         l1 = pL[(128 + bq) * 64 + r];
        float m  = fmaxf(m0, m1);
        float w0 = __expf(m0 - m), w1 = __expf(m1 - m);
        float l  = l0 * w0 + l1 * w1;
        float c0 = pC[((size_t)bq * 64 + r) * 128 + d];
        float c1 = pC[((size_t)(128 + bq) * 64 + r) * 128 + d];
        float v  = (c0 * w0 + c1 * w1) / l;

        int rep = r >> 4, s = r & 15;
        size_t o = ((size_t)(b * SS + s) * HH + kvh * 4 + rep) * HDIM + d;
        Ct[o] = __uint_as_float(f2tf(v));
    }
}

// ---------------- launch ----------------
extern "C" void kernel_launch(void* const* d_in, const int* in_sizes, int n_in,
                              void* d_out, int out_size)
{
    const float* x      = (const float*)d_in[0];
    const float* Wq     = (const float*)d_in[1];
    const float* Wk     = (const float*)d_in[2];
    const float* Wv     = (const float*)d_in[3];
    const float* Wo     = (const float*)d_in[4];
    const float* cacheK = (const float*)d_in[5];
    const float* cacheV = (const float*)d_in[6];
    const int*   spp    = (const int*)  d_in[7];
    float*       out    = (float*)d_out;
    (void)in_sizes; (void)n_in; (void)out_size;

    void *xt, *ct, *qp, *kp, *vp, *pm, *pl, *pc;
    cudaGetSymbolAddress(&xt, g_Xt);   cudaGetSymbolAddress(&ct, g_Ct);
    cudaGetSymbolAddress(&qp, g_Q);    cudaGetSymbolAddress(&kp, g_Kn);
    cudaGetSymbolAddress(&vp, g_Vn);
    cudaGetSymbolAddress(&pm, g_pM);   cudaGetSymbolAddress(&pl, g_pL);
    cudaGetSymbolAddress(&pc, g_pC);

    cudaFuncSetAttribute(tgemm, cudaFuncAttributeMaxDynamicSharedMemorySize, T_SMEM);
    cudaFuncSetAttribute(attn_kernel, cudaFuncAttributeMaxDynamicSharedMemorySize, ATTN_SMEM);

    dim3 blk(256);
    // tf32-round x (weights rounded per-fragment inside tgemm)
    conv_tf32<<<4096, 256>>>(x, (float*)xt, MROWS * DK);

    // fused QKV projection, tf32 single-pass
    tgemm<<<dim3(96, 2), blk, T_SMEM>>>(
        (float*)xt,
        Wq, (float*)qp, 4096,
        Wk, (float*)kp, 1024,
        Wv, (float*)vp, 1024);

    // RoPE on Q and new K
    {
        int total = MROWS * HH * 64 + MROWS * KVH * 64;
        rope_kernel<<<(total + 255) / 256, 256>>>(spp);
    }

    // attention (bf16 hi/lo 3-pass, unchanged) + combine
    attn_kernel<<<dim3(128, 2), blk, ATTN_SMEM>>>(cacheK, cacheV, spp,
                                                  (float*)pm, (float*)pl, (float*)pc);
    combine_kernel<<<128, blk>>>((float*)pm, (float*)pl, (float*)pc, (float*)ct);

    // output projection, tf32 single-pass
    tgemm<<<dim3(64, 2), blk, T_SMEM>>>(
        (float*)ct,
        Wo, out, 4096,
        (const float*)0, (float*)0, 0,
        (const float*)0, (float*)0, 0);
}

// round 12
// speedup vs baseline: 4.7174x; 1.1080x over previous
#include <cuda_runtime.h>
#include <cuda_bf16.h>
#include <math.h>
#include <stdint.h>

// ---------------- problem constants ----------------
#define BB    16
#define SS    16
#define HH    32
#define KVH   8
#define HDIM  128
#define MAXS  4096
#define MROWS 256
#define DK    4096
#define KVLEN 4096

// split-K partial buffer layout
#define PSTR 1572864          // per-half stride (256*6144)
#define QOFF 0
#define KOFF 1048576
#define VOFF 1310720

typedef __nv_bfloat16  bf16;
typedef __nv_bfloat162 bf162;

// ---------------- device scratch ----------------
__device__ float g_Xt[MROWS * DK];      // x, tf32-rounded
__device__ float g_Ct[MROWS * DK];      // ctx, tf32-rounded
__device__ float g_Q [MROWS * 4096];
__device__ float g_Kn[MROWS * 1024];
__device__ float g_Vn[MROWS * 1024];
__device__ float g_Gp[2 * PSTR];        // split-K partials (QKV and Wo reuse)
__device__ float g_pM[2 * 128 * 64], g_pL[2 * 128 * 64];
__device__ float g_pC[2 * 128 * 64 * 128];

// ---------------- PTX helpers ----------------
__device__ __forceinline__ uint32_t smem_u32(const void* p) {
    uint32_t a;
    asm("{ .reg .u64 t; cvta.to.shared.u64 t, %1; cvt.u32.u64 %0, t; }" : "=r"(a) : "l"(p));
    return a;
}
#define LDSM4(r, addr) \
    asm volatile("ldmatrix.sync.aligned.m8n8.x4.shared.b16 {%0,%1,%2,%3}, [%4];" \
        : "=r"((r)[0]), "=r"((r)[1]), "=r"((r)[2]), "=r"((r)[3]) : "r"(addr))
#define LDSM4T(r, addr) \
    asm volatile("ldmatrix.sync.aligned.m8n8.x4.trans.shared.b16 {%0,%1,%2,%3}, [%4];" \
        : "=r"((r)[0]), "=r"((r)[1]), "=r"((r)[2]), "=r"((r)[3]) : "r"(addr))
#define MMA16816(d, a, b0, b1) \
    asm volatile("mma.sync.aligned.m16n8k16.row.col.f32.bf16.bf16.f32 " \
        "{%0,%1,%2,%3}, {%4,%5,%6,%7}, {%8,%9}, {%0,%1,%2,%3};" \
        : "+f"((d)[0]), "+f"((d)[1]), "+f"((d)[2]), "+f"((d)[3]) \
        : "r"((a)[0]), "r"((a)[1]), "r"((a)[2]), "r"((a)[3]), "r"(b0), "r"(b1))
#define MMATF32(d, a, b0, b1) \
    asm volatile("mma.sync.aligned.m16n8k8.row.col.f32.tf32.tf32.f32 " \
        "{%0,%1,%2,%3}, {%4,%5,%6,%7}, {%8,%9}, {%0,%1,%2,%3};" \
        : "+f"((d)[0]), "+f"((d)[1]), "+f"((d)[2]), "+f"((d)[3]) \
        : "r"((a)[0]), "r"((a)[1]), "r"((a)[2]), "r"((a)[3]), "r"(b0), "r"(b1))
#define CP16(dst, src) \
    asm volatile("cp.async.cg.shared.global [%0], [%1], 16;" :: "r"(dst), "l"(src))
#define CP_COMMIT() asm volatile("cp.async.commit_group;" ::: "memory")
#define CP_WAIT0()  asm volatile("cp.async.wait_group 0;" ::: "memory")
#define CP_WAIT1()  asm volatile("cp.async.wait_group 1;" ::: "memory")

__device__ __forceinline__ uint32_t f2tf(float f) {
    uint32_t r;
    asm("cvt.rna.tf32.f32 %0, %1;" : "=r"(r) : "f"(f));
    return r;
}
// hi = truncated-to-bf16 pair (PRMT), lo = bf16-rounded residual pair
__device__ __forceinline__ void split4(float4 v, uint32_t& h01, uint32_t& h23,
                                       uint32_t& l01, uint32_t& l23) {
    uint32_t b0 = __float_as_uint(v.x), b1 = __float_as_uint(v.y);
    uint32_t b2 = __float_as_uint(v.z), b3 = __float_as_uint(v.w);
    h01 = __byte_perm(b0, b1, 0x7632);
    h23 = __byte_perm(b2, b3, 0x7632);
    float r0 = v.x - __uint_as_float(b0 & 0xFFFF0000u);
    float r1 = v.y - __uint_as_float(b1 & 0xFFFF0000u);
    float r2 = v.z - __uint_as_float(b2 & 0xFFFF0000u);
    float r3 = v.w - __uint_as_float(b3 & 0xFFFF0000u);
    asm("cvt.rn.bf16x2.f32 %0, %1, %2;" : "=r"(l01) : "f"(r1), "f"(r0));
    asm("cvt.rn.bf16x2.f32 %0, %1, %2;" : "=r"(l23) : "f"(r3), "f"(r2));
}
__device__ __forceinline__ uint32_t pack_hilo(float a, float b, uint32_t& lo) {
    uint32_t ba = __float_as_uint(a), bb = __float_as_uint(b);
    uint32_t h = __byte_perm(ba, bb, 0x7632);
    float ra = a - __uint_as_float(ba & 0xFFFF0000u);
    float rb = b - __uint_as_float(bb & 0xFFFF0000u);
    asm("cvt.rn.bf16x2.f32 %0, %1, %2;" : "=r"(lo) : "f"(rb), "f"(ra));
    return h;
}

// ---------------- x tf32 pre-rounding ----------------
__global__ void conv_tf32(const float* __restrict__ in, float* __restrict__ outp, int n)
{
    int i = blockIdx.x * blockDim.x + threadIdx.x;
    if (i >= n) return;
    outp[i] = __uint_as_float(f2tf(in[i]));
}

// ---------------- partial-add + RoPE (QKV split-K combine) ----------------
__global__ void rope_add(const float* __restrict__ Gp, const int* __restrict__ spp)
{
    const float* p0 = Gp;
    const float* p1 = Gp + PSTR;
    const int NQP = 524288, NKP = 131072, NVP = 131072;
    int idx = blockIdx.x * blockDim.x + threadIdx.x;
    if (idx >= NQP + NKP + NVP) return;
    const int sp = *spp;

    if (idx < NQP + NKP) {
        float* dst; int nh, i; size_t base;
        if (idx < NQP) { dst = g_Q;  nh = 32; i = idx;       base = QOFF; }
        else           { dst = g_Kn; nh = 8;  i = idx - NQP; base = KOFF; }
        int j = i & 63;
        int h = (i >> 6) % nh;
        int m = i / (64 * nh);
        size_t o = base + ((size_t)m * nh + h) * 128 + 2 * j;
        float xr = p0[o]     + p1[o];
        float xi = p0[o + 1] + p1[o + 1];
        float p     = (float)(sp + (m & 15));
        float theta = powf(10000.0f, -(float)(2 * j) / 128.0f);
        float sn, cs;
        sincosf(p * theta, &sn, &cs);
        size_t od = ((size_t)m * nh + h) * 128 + 2 * j;
        dst[od]     = xr * cs - xi * sn;
        dst[od + 1] = xr * sn + xi * cs;
    } else {
        int vo = (idx - NQP - NKP) * 2;
        size_t o = VOFF + vo;
        g_Vn[vo]     = p0[o]     + p1[o];
        g_Vn[vo + 1] = p0[o + 1] + p1[o + 1];
    }
}

// ---------------- Wo partial add ----------------
__global__ void add_out(const float* __restrict__ Gp, float* __restrict__ outp)
{
    int i = blockIdx.x * blockDim.x + threadIdx.x;
    if (i < MROWS * 4096) outp[i] = Gp[i] + Gp[PSTR + i];
}

// ================= tf32 split-K GEMM: Cpart[z] = A[:, z*2048:(z+1)*2048] @ W-half =================
#define T_STAGE 27648
#define T_SMEM  (3 * T_STAGE)

__global__ __launch_bounds__(256, 2) void tgemm(
    const float* __restrict__ A,
    const float* __restrict__ W0, int N0, int off0,
    const float* __restrict__ W1, int N1, int off1,
    const float* __restrict__ W2, int N2, int off2,
    float* __restrict__ Gp)
{
    extern __shared__ char smg[];
    const int t = threadIdx.x, w = t >> 5, lane = t & 31;
    const int wm = w >> 2, wn = w & 3;          // 2 m-warps x 4 n-warps
    const int bm = blockIdx.y * 128;
    const int z  = blockIdx.z;
    const int koff = z * 2048;

    int xt = blockIdx.x;
    const int t0n = N0 >> 6, t1n = N1 >> 6;
    const float* W; int Nseg, bn, coff;
    if (xt < t0n)            { W = W0; Nseg = N0; bn = xt * 64;               coff = off0; }
    else if (xt < t0n + t1n) { W = W1; Nseg = N1; bn = (xt - t0n) * 64;       coff = off1; }
    else                     { W = W2; Nseg = N2; bn = (xt - t0n - t1n) * 64; coff = off2; }
    float* C = Gp + (size_t)z * PSTR + coff;

    auto copy_stage = [&](int slot, int ch) {
        const int k0 = koff + ch * 32;
        char* base = smg + slot * T_STAGE;
#pragma unroll
        for (int j = 0; j < 6; j++) {
            int idx = j * 256 + t;
            if (idx < 1024) {
                int r = idx >> 3, c = idx & 7;
                const float* src = A + (size_t)(bm + r) * DK + k0 + c * 4;
                CP16(smem_u32(base + r * 144 + c * 16), src);
            } else {
                int q = idx - 1024, r = q >> 4, c = q & 15;
                const float* src = W + (size_t)(k0 + r) * Nseg + bn + c * 4;
                CP16(smem_u32(base + 18432 + r * 288 + c * 16), src);
            }
        }
    };

    float acc[4][2][4];
#pragma unroll
    for (int a = 0; a < 4; a++)
#pragma unroll
        for (int bq = 0; bq < 2; bq++)
#pragma unroll
            for (int cix = 0; cix < 4; cix++) acc[a][bq][cix] = 0.f;

    const int NCH = 2048 / 32;     // 64 chunks per K-half
    copy_stage(0, 0); CP_COMMIT();
    copy_stage(1, 1); CP_COMMIT();

    const int lq = lane >> 2, lr = lane & 3;

    for (int ch = 0; ch < NCH; ch++) {
        if (ch + 1 < NCH) { CP_WAIT1(); } else { CP_WAIT0(); }
        __syncthreads();

        if (ch + 2 < NCH) { copy_stage((ch + 2) % 3, ch + 2); CP_COMMIT(); }

        const float* stA = (const float*)(smg + (ch % 3) * T_STAGE);          // stride 36 f
        const float* stW = (const float*)(smg + (ch % 3) * T_STAGE + 18432);  // stride 72 f

#pragma unroll
        for (int ks = 0; ks < 4; ks++) {
            uint32_t bf[2][2];
#pragma unroll
            for (int tn = 0; tn < 2; tn++) {
                int col = wn * 16 + tn * 8 + lq;
                int kr = ks * 8 + lr;
                bf[tn][0] = f2tf(stW[kr * 72 + col]);
                bf[tn][1] = f2tf(stW[(kr + 4) * 72 + col]);
            }
#pragma unroll
            for (int mt = 0; mt < 4; mt++) {
                int ar = wm * 64 + mt * 16 + lq;
                int ac = ks * 8 + lr;
                uint32_t af[4];
                af[0] = __float_as_uint(stA[ar * 36 + ac]);
                af[1] = __float_as_uint(stA[(ar + 8) * 36 + ac]);
                af[2] = __float_as_uint(stA[ar * 36 + ac + 4]);
                af[3] = __float_as_uint(stA[(ar + 8) * 36 + ac + 4]);
#pragma unroll
                for (int tn = 0; tn < 2; tn++)
                    MMATF32(acc[mt][tn], af, bf[tn][0], bf[tn][1]);
            }
        }
    }

#pragma unroll
    for (int mt = 0; mt < 4; mt++) {
        int r = bm + wm * 64 + mt * 16 + lq;
#pragma unroll
        for (int tn = 0; tn < 2; tn++) {
            int c = bn + wn * 16 + tn * 8 + lr * 2;
            *(float2*)&C[(size_t)r * Nseg + c]       = make_float2(acc[mt][tn][0], acc[mt][tn][1]);
            *(float2*)&C[(size_t)(r + 8) * Nseg + c] = make_float2(acc[mt][tn][2], acc[mt][tn][3]);
        }
    }
}

// ================= register-resident HMMA flash attention =================
#define AT_QH  0
#define AT_KH  34816
#define AT_VH  52224
#define AT_RAW 69632
#define AT_ML  103424
#define ATTN_SMEM 104448
#define NCHA 64

__global__ __launch_bounds__(256, 2) void attn_kernel(const float* __restrict__ cacheK,
                                                      const float* __restrict__ cacheV,
                                                      const int* __restrict__ spp,
                                                      float* __restrict__ pM,
                                                      float* __restrict__ pL,
                                                      float* __restrict__ pC)
{
    extern __shared__ char sm[];
    char* qh = sm + AT_QH;
    char* kh = sm + AT_KH;
    char* vh = sm + AT_VH;
    char* raw = sm + AT_RAW;
    float* mlb = (float*)(sm + AT_ML);

    const int t = threadIdx.x, w = t >> 5, lane = t & 31;
    const int b = blockIdx.x >> 3, kvh = blockIdx.x & 7;
    const int half = blockIdx.y;
    const int pb = half * 128 + blockIdx.x;
    const int kvb = half * 2048;
    const int sp = *spp;
    const int wq = w & 3, gk = w >> 2;

    const uint32_t u_qh = smem_u32(qh), u_kh = smem_u32(kh), u_vh = smem_u32(vh);

    auto prefetch = [&](int chunk) {
        const int t0 = kvb + chunk * 32;
#pragma unroll
        for (int j = 0; j < 8; j++) {
            int idx = j * 256 + t;
            int tensor = idx >> 10;
            int i = idx & 1023;
            int r = i >> 5, c4 = i & 31;
            int tk = t0 + r;
            const float* src;
            if (tensor == 0)
                src = (tk < sp)
                    ? cacheK + (((size_t)b * MAXS + tk) * KVH + kvh) * HDIM + c4 * 4
                    : g_Kn + (((size_t)b * SS + (tk - sp)) * KVH + kvh) * HDIM + c4 * 4;
            else
                src = (tk < sp)
                    ? cacheV + (((size_t)b * MAXS + tk) * KVH + kvh) * HDIM + c4 * 4
                    : g_Vn + (((size_t)b * SS + (tk - sp)) * KVH + kvh) * HDIM + c4 * 4;
            CP16(smem_u32(raw + tensor * 16896 + r * 528 + c4 * 16), src);
        }
    };

    prefetch(0); CP_COMMIT();

    // Q load + hi/lo split into smem
#pragma unroll
    for (int j = 0; j < 8; j++) {
        int idx = j * 256 + t;
        int r = idx >> 5, c4 = idx & 31;
        const float4 v = *(const float4*)(g_Q +
            (((size_t)b * SS + (r & 15)) * HH + kvh * 4 + (r >> 4)) * HDIM + c4 * 4);
        uint32_t h01, h23, l01, l23;
        split4(v, h01, h23, l01, l23);
        char* hp = qh + r * 272 + c4 * 8;
        *(uint2*)(hp)         = make_uint2(h01, h23);
        *(uint2*)(hp + 17408) = make_uint2(l01, l23);
    }

    const int r0 = wq * 16 + (lane >> 2);
    const int r1 = r0 + 8;
    float mA = __int_as_float(0xff800000), mB = mA;
    float lA = 0.f, lB = 0.f;

    float oacc[16][4];
#pragma unroll
    for (int nt = 0; nt < 16; nt++)
#pragma unroll
        for (int cix = 0; cix < 4; cix++) oacc[nt][cix] = 0.f;

    const float scale = 0.08838834764831845f;
    const uint32_t a_lane = (lane & 15) * 272 + (lane >> 4) * 16;
    const uint32_t b_row  = (lane & 7) + ((lane >> 4) << 3);
    const uint32_t b_col  = ((lane >> 3) & 1) * 16;

    for (int ch = 0; ch < NCHA; ch++) {
        CP_WAIT0();
        __syncthreads();

        // K/V fp32 -> bf16 hi/lo tiles (PRMT split)
#pragma unroll
        for (int j = 0; j < 8; j++) {
            int idx = j * 256 + t;
            int tensor = idx >> 10;
            int i = idx & 1023;
            int r = i >> 5, c4 = i & 31;
            float4 v = *(const float4*)(raw + tensor * 16896 + r * 528 + c4 * 16);
            uint32_t h01, h23, l01, l23;
            split4(v, h01, h23, l01, l23);
            char* hp = (tensor ? vh : kh) + r * 272 + c4 * 8;
            *(uint2*)(hp)        = make_uint2(h01, h23);
            *(uint2*)(hp + 8704) = make_uint2(l01, l23);
        }
        __syncthreads();

        if (ch + 1 < NCHA) { prefetch(ch + 1); CP_COMMIT(); }

        // ---- S = Q K^T, 3 independent accumulator sets (hi*hi, hi*lo, lo*hi) ----
        float aHH[2][4], aHL[2][4], aLH[2][4];
#pragma unroll
        for (int tn = 0; tn < 2; tn++)
#pragma unroll
            for (int cix = 0; cix < 4; cix++) {
                aHH[tn][cix] = 0.f; aHL[tn][cix] = 0.f; aLH[tn][cix] = 0.f;
            }

        const uint32_t kb = u_kh + (gk * 16 + b_row) * 272 + b_col;
#pragma unroll
        for (int ks = 0; ks < 8; ks++) {
            const int ko = ks * 32;
            uint32_t bh_[4], bl_[4];
            LDSM4(bh_, kb + ko);
            LDSM4(bl_, kb + ko + 8704);
            uint32_t aa = u_qh + (wq * 16) * 272 + a_lane + ko;
            uint32_t ah_[4], al_[4];
            LDSM4(ah_, aa);
            LDSM4(al_, aa + 17408);
#pragma unroll
            for (int tn = 0; tn < 2; tn++) {
                MMA16816(aHH[tn], ah_, bh_[tn * 2], bh_[tn * 2 + 1]);
                MMA16816(aHL[tn], ah_, bl_[tn * 2], bl_[tn * 2 + 1]);
                MMA16816(aLH[tn], al_, bh_[tn * 2], bh_[tn * 2 + 1]);
            }
        }

        float s00 = (aHH[0][0] + aHL[0][0] + aLH[0][0]) * scale;
        float s01 = (aHH[0][1] + aHL[0][1] + aLH[0][1]) * scale;
        float s02 = (aHH[1][0] + aHL[1][0] + aLH[1][0]) * scale;
        float s03 = (aHH[1][1] + aHL[1][1] + aLH[1][1]) * scale;
        float s10 = (aHH[0][2] + aHL[0][2] + aLH[0][2]) * scale;
        float s11 = (aHH[0][3] + aHL[0][3] + aLH[0][3]) * scale;
        float s12 = (aHH[1][2] + aHL[1][2] + aLH[1][2]) * scale;
        float s13 = (aHH[1][3] + aHL[1][3] + aLH[1][3]) * scale;

        float mx0 = fmaxf(fmaxf(s00, s01), fmaxf(s02, s03));
        float mx1 = fmaxf(fmaxf(s10, s11), fmaxf(s12, s13));
#pragma unroll
        for (int o = 1; o <= 2; o <<= 1) {
            mx0 = fmaxf(mx0, __shfl_xor_sync(0xffffffffu, mx0, o));
            mx1 = fmaxf(mx1, __shfl_xor_sync(0xffffffffu, mx1, o));
        }
        float m0n = fmaxf(mA, mx0), m1n = fmaxf(mB, mx1);
        float c0 = __expf(mA - m0n), c1 = __expf(mB - m1n);

        float e00 = __expf(s00 - m0n), e01 = __expf(s01 - m0n);
        float e02 = __expf(s02 - m0n), e03 = __expf(s03 - m0n);
        float e10 = __expf(s10 - m1n), e11 = __expf(s11 - m1n);
        float e12 = __expf(s12 - m1n), e13 = __expf(s13 - m1n);

        float sum0 = e00 + e01 + e02 + e03;
        float sum1 = e10 + e11 + e12 + e13;
#pragma unroll
        for (int o = 1; o <= 2; o <<= 1) {
            sum0 += __shfl_xor_sync(0xffffffffu, sum0, o);
            sum1 += __shfl_xor_sync(0xffffffffu, sum1, o);
        }
        lA = lA * c0 + sum0;  mA = m0n;
        lB = lB * c1 + sum1;  mB = m1n;

        uint32_t ph_[4], pl_[4];
        ph_[0] = pack_hilo(e00, e01, pl_[0]);
        ph_[1] = pack_hilo(e10, e11, pl_[1]);
        ph_[2] = pack_hilo(e02, e03, pl_[2]);
        ph_[3] = pack_hilo(e12, e13, pl_[3]);

#pragma unroll
        for (int nt = 0; nt < 16; nt++) {
            oacc[nt][0] *= c0; oacc[nt][1] *= c0;
            oacc[nt][2] *= c1; oacc[nt][3] *= c1;
        }

        // ---- O += P V, 2-stage V-fragment pipeline ----
        const uint32_t vb = u_vh + (gk * 16 + (lane & 15)) * 272 + (lane >> 4) * 16;
        uint32_t vhA[4], vlA[4], vhB[4], vlB[4];
        LDSM4T(vhA, vb);
        LDSM4T(vlA, vb + 8704);
#pragma unroll
        for (int nc = 0; nc < 8; nc++) {
            uint32_t* ch_ = (nc & 1) ? vhB : vhA;
            uint32_t* cl_ = (nc & 1) ? vlB : vlA;
            uint32_t* nh_ = (nc & 1) ? vhA : vhB;
            uint32_t* nl_ = (nc & 1) ? vlA : vlB;
            if (nc < 7) {
                LDSM4T(nh_, vb + (nc + 1) * 32);
                LDSM4T(nl_, vb + (nc + 1) * 32 + 8704);
            }
#pragma unroll
            for (int sub = 0; sub < 2; sub++) {
                int nt = nc * 2 + sub;
                MMA16816(oacc[nt], ph_, ch_[sub * 2], ch_[sub * 2 + 1]);
                MMA16816(oacc[nt], ph_, cl_[sub * 2], cl_[sub * 2 + 1]);
                MMA16816(oacc[nt], pl_, ch_[sub * 2], ch_[sub * 2 + 1]);
            }
        }
    }

    // ---- epilogue: merge k-groups, write partials ----
    __syncthreads();
    float* rowbuf = (float*)raw;
    if ((lane & 3) == 0) {
        mlb[(gk * 64 + r0) * 2 + 0] = mA;  mlb[(gk * 64 + r0) * 2 + 1] = lA;
        mlb[(gk * 64 + r1) * 2 + 0] = mB;  mlb[(gk * 64 + r1) * 2 + 1] = lB;
    }
    if (gk == 1) {
#pragma unroll
        for (int nt = 0; nt < 16; nt++) {
            int c = nt * 8 + (lane & 3) * 2;
            *(float2*)&rowbuf[r0 * 128 + c] = make_float2(oacc[nt][0], oacc[nt][1]);
            *(float2*)&rowbuf[r1 * 128 + c] = make_float2(oacc[nt][2], oacc[nt][3]);
        }
    }
    __syncthreads();
    if (gk == 0) {
        float m1r0 = mlb[(64 + r0) * 2 + 0], l1r0 = mlb[(64 + r0) * 2 + 1];
        float m1r1 = mlb[(64 + r1) * 2 + 0], l1r1 = mlb[(64 + r1) * 2 + 1];
        float M0 = fmaxf(mA, m1r0), M1 = fmaxf(mB, m1r1);
        float w00 = __expf(mA - M0), w01 = __expf(m1r0 - M0);
        float w10 = __expf(mB - M1), w11 = __expf(m1r1 - M1);
        float L0 = lA * w00 + l1r0 * w01;
        float L1 = lB * w10 + l1r1 * w11;
#pragma unroll
        for (int nt = 0; nt < 16; nt++) {
            int c = nt * 8 + (lane & 3) * 2;
            float2 o1a = *(float2*)&rowbuf[r0 * 128 + c];
            float2 o1b = *(float2*)&rowbuf[r1 * 128 + c];
            *(float2*)&pC[((size_t)pb * 64 + r0) * 128 + c] =
                make_float2(oacc[nt][0] * w00 + o1a.x * w01,
                            oacc[nt][1] * w00 + o1a.y * w01);
            *(float2*)&pC[((size_t)pb * 64 + r1) * 128 + c] =
                make_float2(oacc[nt][2] * w10 + o1b.x * w11,
                            oacc[nt][3] * w10 + o1b.y * w11);
        }
        if ((lane & 3) == 0) {
            pM[pb * 64 + r0] = M0;  pL[pb * 64 + r0] = L0;
            pM[pb * 64 + r1] = M1;  pL[pb * 64 + r1] = L1;
        }
    }
}

// ---------------- combine halves -> tf32-rounded fp32 ctx ----------------
__global__ void combine_kernel(const float* __restrict__ pM, const float* __restrict__ pL,
                               const float* __restrict__ pC, float* __restrict__ Ct)
{
    const int bq  = blockIdx.x;
    const int b   = bq >> 3;
    const int kvh = bq & 7;
    const int t   = threadIdx.x;

    for (int idx = t; idx < 64 * 128; idx += 256) {
        int r = idx >> 7;
        int d = idx & 127;
        float m0 = pM[bq * 64 + r],         m1 = pM[(128 + bq) * 64 + r];
        float l0 = pL[bq * 64 + r],         l1 = pL[(128 + bq) * 64 + r];
        float m  = fmaxf(m0, m1);
        float w0 = __expf(m0 - m), w1 = __expf(m1 - m);
        float l  = l0 * w0 + l1 * w1;
        float c0 = pC[((size_t)bq * 64 + r) * 128 + d];
        float c1 = pC[((size_t)(128 + bq) * 64 + r) * 128 + d];
        float v  = (c0 * w0 + c1 * w1) / l;

        int rep = r >> 4, s = r & 15;
        size_t o = ((size_t)(b * SS + s) * HH + kvh * 4 + rep) * HDIM + d;
        Ct[o] = __uint_as_float(f2tf(v));
    }
}

// ---------------- launch ----------------
extern "C" void kernel_launch(void* const* d_in, const int* in_sizes, int n_in,
                              void* d_out, int out_size)
{
    const float* x      = (const float*)d_in[0];
    const float* Wq     = (const float*)d_in[1];
    const float* Wk     = (const float*)d_in[2];
    const float* Wv     = (const float*)d_in[3];
    const float* Wo     = (const float*)d_in[4];
    const float* cacheK = (const float*)d_in[5];
    const float* cacheV = (const float*)d_in[6];
    const int*   spp    = (const int*)  d_in[7];
    float*       out    = (float*)d_out;
    (void)in_sizes; (void)n_in; (void)out_size;

    void *xt, *ct, *gp, *pm, *pl, *pc;
    cudaGetSymbolAddress(&xt, g_Xt);   cudaGetSymbolAddress(&ct, g_Ct);
    cudaGetSymbolAddress(&gp, g_Gp);
    cudaGetSymbolAddress(&pm, g_pM);   cudaGetSymbolAddress(&pl, g_pL);
    cudaGetSymbolAddress(&pc, g_pC);

    cudaFuncSetAttribute(tgemm, cudaFuncAttributeMaxDynamicSharedMemorySize, T_SMEM);
    cudaFuncSetAttribute(attn_kernel, cudaFuncAttributeMaxDynamicSharedMemorySize, ATTN_SMEM);

    dim3 blk(256);
    // tf32-round x
    conv_tf32<<<4096, 256>>>(x, (float*)xt, MROWS * DK);

    // fused QKV projection, split-K x2 -> partials
    tgemm<<<dim3(96, 2, 2), blk, T_SMEM>>>(
        (float*)xt,
        Wq, 4096, QOFF,
        Wk, 1024, KOFF,
        Wv, 1024, VOFF,
        (float*)gp);

    // partial add + RoPE -> g_Q / g_Kn / g_Vn
    rope_add<<<3072, 256>>>((float*)gp, spp);

    // attention + combine
    attn_kernel<<<dim3(128, 2), blk, ATTN_SMEM>>>(cacheK, cacheV, spp,
                                                  (float*)pm, (float*)pl, (float*)pc);
    combine_kernel<<<128, blk>>>((float*)pm, (float*)pl, (float*)pc, (float*)ct);

    // output projection, split-K x2 -> partials, then add
    tgemm<<<dim3(64, 2, 2), blk, T_SMEM>>>(
        (float*)ct,
        Wo, 4096, 0,
        (const float*)0, 0, 0,
        (const float*)0, 0, 0,
        (float*)gp);
    add_out<<<4096, 256>>>((float*)gp, out);
}